// round 4
// baseline (speedup 1.0000x reference)
#include <cuda_runtime.h>
#include <math.h>

// Problem constants (B=8, C=256, H=W=128, win_n=4, shift=16)
#define HW   16384      // 128*128
#define IMG  128
#define NREG 29
#define TOTPIX 229376   // sum over regions of N * 8 batches
#define COUT 448        // 256 V + 96 Pq(3 taps x 32) + 96 Pk

// Region tables: 12 win (rows 1..3 x cols 0..3), 9 shift-inner, 8 borders
__constant__ int c_h0[NREG] = {32,32,32,32, 64,64,64,64, 96,96,96,96,
                               16,16,16, 48,48,48, 80,80,80,
                               0,0,0, 16,16, 112,112,112};
__constant__ int c_w0[NREG] = {0,32,64,96, 0,32,64,96, 0,32,64,96,
                               16,48,80, 16,48,80, 16,48,80,
                               0,16,112, 0,112, 0,16,112};
__constant__ int c_Hr[NREG] = {32,32,32,32,32,32,32,32,32,32,32,32,
                               32,32,32,32,32,32,32,32,32,
                               16,16,16, 96,96, 16,16,16};
__constant__ int c_Wr[NREG] = {32,32,32,32,32,32,32,32,32,32,32,32,
                               32,32,32,32,32,32,32,32,32,
                               16,96,16, 16,16, 16,96,16};
__constant__ int c_N[NREG]  = {1024,1024,1024,1024,1024,1024,1024,1024,1024,1024,1024,1024,
                               1024,1024,1024,1024,1024,1024,1024,1024,1024,
                               256,1536,256, 1536,1536, 256,1536,256};
__constant__ int c_base[NREG] = {0,8192,16384,24576,32768,40960,49152,57344,65536,73728,81920,90112,
                                 98304,106496,114688,122880,131072,139264,147456,155648,163840,
                                 172032,174080,186368, 188416,200704, 212992,215040,227328};

// Scratch (__device__ globals: the allowed scratch mechanism; zero-init bss)
static __device__ float g_Wall[256 * COUT];                  // [ci][co]
static __device__ float g_V  [(size_t)TOTPIX * 256];         // [pix][256]
static __device__ float g_PQK[(size_t)TOTPIX * 192];         // [pix][Pq0,Pq1,Pq2,Pk0,Pk1,Pk2 x32]
static __device__ float g_Q  [(size_t)TOTPIX * 32];
static __device__ float g_K  [(size_t)TOTPIX * 32];
static __device__ int   g_pix[TOTPIX];                       // addr of x[b,0,h,w]
static __device__ float g_qsc[32], g_qof[32], g_ksc[32], g_kof[32];

// ---------------------------------------------------------------- prep kernels
__global__ void prep_wall(const float* __restrict__ Wq, const float* __restrict__ Wk,
                          const float* __restrict__ Wv) {
    int idx = blockIdx.x * 256 + threadIdx.x;
    if (idx >= 256 * COUT) return;
    int co = idx >> 8, ci = idx & 255;
    float v;
    if (co < 256)       v = Wv[co * 256 + ci];                               // 1x1 conv
    else if (co < 352) { int t = (co - 256) >> 5, c8 = (co - 256) & 31;
                         v = Wq[(c8 * 256 + ci) * 3 + t]; }                  // 1x3 taps
    else               { int t = (co - 352) >> 5, c8 = (co - 352) & 31;
                         v = Wk[(c8 * 256 + ci) * 3 + t]; }                  // 3x1 taps
    g_Wall[ci * COUT + co] = v;
}

__global__ void prep_bn(const float* bq, const float* qs, const float* qo, const float* qm, const float* qv,
                        const float* bk, const float* ks, const float* ko, const float* km, const float* kv) {
    int c = threadIdx.x;
    if (c >= 32) return;
    float sc = qs[c] * rsqrtf(qv[c] + 1e-5f);
    g_qsc[c] = sc;
    g_qof[c] = bq[c] * sc + qo[c] - qm[c] * sc;   // bn(conv+b) = conv*sc + (b*sc + o - m*sc)
    sc = ks[c] * rsqrtf(kv[c] + 1e-5f);
    g_ksc[c] = sc;
    g_kof[c] = bk[c] * sc + ko[c] - km[c] * sc;
}

__global__ void prep_pix() {
    int inst = blockIdx.y;
    int region = inst >> 3, b = inst & 7;
    int N = c_N[region];
    int n = blockIdx.x * 256 + threadIdx.x;
    if (n >= N) return;
    int Wr = c_Wr[region];
    int h = n / Wr, w = n - h * Wr;
    g_pix[c_base[region] + b * N + n] = b * (256 * HW) + (c_h0[region] + h) * IMG + c_w0[region] + w;
}

__global__ void copy_x(const float4* __restrict__ x, float4* __restrict__ o) {
    int i = blockIdx.x * blockDim.x + threadIdx.x;
    int stride = gridDim.x * blockDim.x;
    for (; i < 8388608; i += stride) o[i] = x[i];   // 8*256*128*128/4
}

// ------------------------------------------------- QKV GEMM: [pix,256]@[256,448]
__global__ __launch_bounds__(128) void qkv_gemm(const float* __restrict__ x,
                                                const float* __restrict__ bv) {
    int inst = blockIdx.z;
    int region = inst >> 3, b = inst & 7;
    int N = c_N[region];
    int m0 = blockIdx.y * 64;
    if (m0 >= N) return;
    int pb = c_base[region] + b * N;
    int n0 = blockIdx.x * 64;

    __shared__ float As[16][64];
    __shared__ float Bs[16][64];
    __shared__ int pas[64];
    int tid = threadIdx.x;
    if (tid < 64) pas[tid] = g_pix[pb + m0 + tid];
    __syncthreads();

    float acc[4][8];
#pragma unroll
    for (int i = 0; i < 4; i++)
#pragma unroll
        for (int j = 0; j < 8; j++) acc[i][j] = 0.f;

    int tm = tid & 15, tn = tid >> 4;
    for (int k0 = 0; k0 < 256; k0 += 16) {
#pragma unroll
        for (int r = 0; r < 8; r++) {              // A: 64 pix x 16 ci
            int idx = tid + r * 128;
            int m = idx & 63, kk = idx >> 6;
            As[kk][m] = x[pas[m] + (k0 + kk) * HW];
        }
#pragma unroll
        for (int r = 0; r < 8; r++) {              // B: 16 ci x 64 co
            int idx = tid + r * 128;
            int n = idx & 63, kk = idx >> 6;
            Bs[kk][n] = g_Wall[(k0 + kk) * COUT + n0 + n];
        }
        __syncthreads();
#pragma unroll
        for (int kk = 0; kk < 16; kk++) {
            float4 a  = *(float4*)&As[kk][tm * 4];
            float4 b0 = *(float4*)&Bs[kk][tn * 8];
            float4 b1 = *(float4*)&Bs[kk][tn * 8 + 4];
            float av[4] = {a.x, a.y, a.z, a.w};
            float bw[8] = {b0.x, b0.y, b0.z, b0.w, b1.x, b1.y, b1.z, b1.w};
#pragma unroll
            for (int i = 0; i < 4; i++)
#pragma unroll
                for (int j = 0; j < 8; j++) acc[i][j] = fmaf(av[i], bw[j], acc[i][j]);
        }
        __syncthreads();
    }
#pragma unroll
    for (int i = 0; i < 4; i++) {
        size_t m = (size_t)(pb + m0 + tm * 4 + i);
#pragma unroll
        for (int j = 0; j < 8; j++) {
            int co = n0 + tn * 8 + j;
            if (co < 256) g_V[m * 256 + co] = acc[i][j] + bv[co];
            else          g_PQK[m * 192 + (co - 256)] = acc[i][j];
        }
    }
}

// ----------------------------- combine conv taps (window-local padding) + BN + ReLU
__global__ void combine_qk() {
    int inst = blockIdx.y;
    int region = inst >> 3, b = inst & 7;
    int N = c_N[region];
    int idx = blockIdx.x * 256 + threadIdx.x;
    int n = idx >> 5;
    if (n >= N) return;
    int c8 = idx & 31;
    int Wr = c_Wr[region], Hr = c_Hr[region];
    int pb = c_base[region] + b * N;
    int h = n / Wr, w = n - h * Wr;
    size_t rowp = (size_t)(pb + n) * 192;

    // q[h,w] = Pq0[h,w-1] + Pq1[h,w] + Pq2[h,w+1]   (zero pad at region edge)
    float q = g_PQK[rowp + 32 + c8];
    if (w > 0)      q += g_PQK[rowp - 192 + c8];
    if (w < Wr - 1) q += g_PQK[rowp + 192 + 64 + c8];
    g_Q[(size_t)(pb + n) * 32 + c8] = fmaxf(fmaf(q, g_qsc[c8], g_qof[c8]), 0.f);

    // k[h,w] = Pk0[h-1,w] + Pk1[h,w] + Pk2[h+1,w]
    float k = g_PQK[rowp + 96 + 32 + c8];
    if (h > 0)      k += g_PQK[rowp - (size_t)Wr * 192 + 96 + c8];
    if (h < Hr - 1) k += g_PQK[rowp + (size_t)Wr * 192 + 96 + 64 + c8];
    g_K[(size_t)(pb + n) * 32 + c8] = fmaxf(fmaf(k, g_ksc[c8], g_kof[c8]), 0.f);
}

// ------------------------------------------- flash attention, d_qk=32, d_v=256
__global__ __launch_bounds__(256) void attn(const float* __restrict__ gamma,
                                            float* __restrict__ out) {
    int inst = blockIdx.y;
    int region = inst >> 3, b = inst & 7;
    int N = c_N[region];
    int n0 = blockIdx.x * 32;
    if (n0 >= N) return;
    int pb = c_base[region] + b * N;

    __shared__ float Qs[32 * 33];     // padded: conflict-free column reads
    __shared__ float Ks[32 * 32];
    __shared__ float Vs[32 * 256];
    __shared__ float Ps[32 * 33];
    __shared__ float rmax[32], rsum[32], rscale[32];
    __shared__ int pas[32];

    int tid = threadIdx.x;
#pragma unroll
    for (int r = 0; r < 4; r++) {
        int idx = tid + r * 256;
        int n = idx >> 5, k = idx & 31;
        Qs[n * 33 + k] = g_Q[(size_t)(pb + n0 + n) * 32 + k];
    }
    if (tid < 32) {
        rmax[tid] = -1e30f; rsum[tid] = 0.f;
        pas[tid] = g_pix[pb + n0 + tid];
    }
    float acc[4][8];
#pragma unroll
    for (int i = 0; i < 4; i++)
#pragma unroll
        for (int j = 0; j < 8; j++) acc[i][j] = 0.f;

    int sn = tid & 31, smg = tid >> 5;   // S-compute mapping
    int tn = tid & 7,  tc  = tid >> 3;   // PV mapping (lanes vary n -> coalesced epilogue)

    int nmt = N >> 5;
    for (int mt = 0; mt < nmt; mt++) {
        int mb = pb + mt * 32;
        __syncthreads();
        {
            int m = tid >> 3, c4 = tid & 7;
            *(float4*)&Ks[m * 32 + c4 * 4] = *(const float4*)&g_K[(size_t)(mb + m) * 32 + c4 * 4];
        }
#pragma unroll
        for (int r = 0; r < 8; r++) {
            int idx = tid + r * 256;
            int m = idx >> 6, c4 = idx & 63;
            *(float4*)&Vs[m * 256 + c4 * 4] = *(const float4*)&g_V[(size_t)(mb + m) * 256 + c4 * 4];
        }
        __syncthreads();
        {   // S[n][m] = sum_k Q[n][k]*K[m][k]; thread: 1 n x 4 m
            const float* qrow = &Qs[sn * 33];
            const float* k0r = &Ks[(smg * 4 + 0) * 32];
            const float* k1r = &Ks[(smg * 4 + 1) * 32];
            const float* k2r = &Ks[(smg * 4 + 2) * 32];
            const float* k3r = &Ks[(smg * 4 + 3) * 32];
            float s0 = 0, s1 = 0, s2 = 0, s3 = 0;
#pragma unroll
            for (int k = 0; k < 32; k++) {
                float q = qrow[k];
                s0 = fmaf(q, k0r[k], s0);
                s1 = fmaf(q, k1r[k], s1);
                s2 = fmaf(q, k2r[k], s2);
                s3 = fmaf(q, k3r[k], s3);
            }
            Ps[sn * 33 + smg * 4 + 0] = s0;
            Ps[sn * 33 + smg * 4 + 1] = s1;
            Ps[sn * 33 + smg * 4 + 2] = s2;
            Ps[sn * 33 + smg * 4 + 3] = s3;
        }
        __syncthreads();
        if (tid < 32) {                       // online softmax per row
            float* prow = &Ps[tid * 33];
            float mx = rmax[tid];
            float ml = -1e30f;
#pragma unroll
            for (int m = 0; m < 32; m++) ml = fmaxf(ml, prow[m]);
            float nm = fmaxf(mx, ml);
            float sc = __expf(mx - nm);
            float s = rsum[tid] * sc;
#pragma unroll
            for (int m = 0; m < 32; m++) {
                float p = __expf(prow[m] - nm);
                prow[m] = p;
                s += p;
            }
            rsum[tid] = s; rmax[tid] = nm; rscale[tid] = sc;
        }
        __syncthreads();
#pragma unroll
        for (int i = 0; i < 4; i++) {         // rescale accumulators
            float sc = rscale[tn * 4 + i];
#pragma unroll
            for (int j = 0; j < 8; j++) acc[i][j] *= sc;
        }
#pragma unroll
        for (int m = 0; m < 32; m++) {        // acc += P * V
            float4 v0 = *(float4*)&Vs[m * 256 + tc * 8];
            float4 v1 = *(float4*)&Vs[m * 256 + tc * 8 + 4];
#pragma unroll
            for (int i = 0; i < 4; i++) {
                float p = Ps[(tn * 4 + i) * 33 + m];
                acc[i][0] = fmaf(p, v0.x, acc[i][0]);
                acc[i][1] = fmaf(p, v0.y, acc[i][1]);
                acc[i][2] = fmaf(p, v0.z, acc[i][2]);
                acc[i][3] = fmaf(p, v0.w, acc[i][3]);
                acc[i][4] = fmaf(p, v1.x, acc[i][4]);
                acc[i][5] = fmaf(p, v1.y, acc[i][5]);
                acc[i][6] = fmaf(p, v1.z, acc[i][6]);
                acc[i][7] = fmaf(p, v1.w, acc[i][7]);
            }
        }
    }
    __syncthreads();
    float g = 0.5f * gamma[0];                // (x0+x1)/2: each region delta halved
#pragma unroll
    for (int i = 0; i < 4; i++) {
        int n = tn * 4 + i;
        float f = g / rsum[n];
        int pa = pas[n];
#pragma unroll
        for (int j = 0; j < 8; j++) {
            atomicAdd(&out[pa + (tc * 8 + j) * HW], acc[i][j] * f);
        }
    }
}

// ---------------------------------------------------------------- launcher
extern "C" void kernel_launch(void* const* d_in, const int* in_sizes, int n_in,
                              void* d_out, int out_size) {
    const float* x   = (const float*)d_in[0];
    const float* Wq  = (const float*)d_in[1];
    const float* bq  = (const float*)d_in[2];
    const float* q_s = (const float*)d_in[3];
    const float* q_o = (const float*)d_in[4];
    const float* q_m = (const float*)d_in[5];
    const float* q_v = (const float*)d_in[6];
    const float* Wk  = (const float*)d_in[7];
    const float* bk  = (const float*)d_in[8];
    const float* k_s = (const float*)d_in[9];
    const float* k_o = (const float*)d_in[10];
    const float* k_m = (const float*)d_in[11];
    const float* k_v = (const float*)d_in[12];
    const float* Wv  = (const float*)d_in[13];
    const float* bv  = (const float*)d_in[14];
    const float* gam = (const float*)d_in[15];
    float* out = (float*)d_out;

    prep_wall<<<448, 256>>>(Wq, Wk, Wv);
    prep_bn<<<1, 32>>>(bq, q_s, q_o, q_m, q_v, bk, k_s, k_o, k_m, k_v);
    prep_pix<<<dim3(6, 232), 256>>>();
    copy_x<<<4096, 256>>>((const float4*)x, (float4*)out);
    qkv_gemm<<<dim3(7, 24, 232), 128>>>(x, bv);
    combine_qk<<<dim3(192, 232), 256>>>();
    attn<<<dim3(48, 232), 256>>>(gam, out);
}

// round 5
// speedup vs baseline: 1.0417x; 1.0417x over previous
#include <cuda_runtime.h>
#include <math.h>

// Problem constants (B=8, C=256, H=W=128, win_n=4, shift=16)
#define HW   16384      // 128*128
#define IMG  128
#define NREG 29
#define TOTPIX 229376   // sum over regions of N * 8 batches
#define COUT 448        // 256 V + 96 Pq(3 taps x 32) + 96 Pk

typedef unsigned long long u64;

// ---- packed fp32x2 helpers (FFMA2 path: ptxas never auto-fuses; PTX-only) ----
__device__ __forceinline__ u64 ffma2(u64 a, u64 b, u64 c) {
    u64 d; asm("fma.rn.f32x2 %0, %1, %2, %3;" : "=l"(d) : "l"(a), "l"(b), "l"(c)); return d;
}
__device__ __forceinline__ u64 fmul2(u64 a, u64 b) {
    u64 d; asm("mul.rn.f32x2 %0, %1, %2;" : "=l"(d) : "l"(a), "l"(b)); return d;
}
__device__ __forceinline__ u64 dup2(float x) {
    u64 u; asm("mov.b64 %0, {%1,%1};" : "=l"(u) : "f"(x)); return u;
}
__device__ __forceinline__ float2 u2f(u64 u) {
    float2 f; asm("mov.b64 {%0,%1}, %2;" : "=f"(f.x), "=f"(f.y) : "l"(u)); return f;
}
__device__ __forceinline__ u64 d2u(double x) { return (u64)__double_as_longlong(x); }

// Region tables: 12 win (rows 1..3 x cols 0..3), 9 shift-inner, 8 borders
__constant__ int c_h0[NREG] = {32,32,32,32, 64,64,64,64, 96,96,96,96,
                               16,16,16, 48,48,48, 80,80,80,
                               0,0,0, 16,16, 112,112,112};
__constant__ int c_w0[NREG] = {0,32,64,96, 0,32,64,96, 0,32,64,96,
                               16,48,80, 16,48,80, 16,48,80,
                               0,16,112, 0,112, 0,16,112};
__constant__ int c_Hr[NREG] = {32,32,32,32,32,32,32,32,32,32,32,32,
                               32,32,32,32,32,32,32,32,32,
                               16,16,16, 96,96, 16,16,16};
__constant__ int c_Wr[NREG] = {32,32,32,32,32,32,32,32,32,32,32,32,
                               32,32,32,32,32,32,32,32,32,
                               16,96,16, 16,16, 16,96,16};
__constant__ int c_N[NREG]  = {1024,1024,1024,1024,1024,1024,1024,1024,1024,1024,1024,1024,
                               1024,1024,1024,1024,1024,1024,1024,1024,1024,
                               256,1536,256, 1536,1536, 256,1536,256};
__constant__ int c_base[NREG] = {0,8192,16384,24576,32768,40960,49152,57344,65536,73728,81920,90112,
                                 98304,106496,114688,122880,131072,139264,147456,155648,163840,
                                 172032,174080,186368, 188416,200704, 212992,215040,227328};

// Scratch (__device__ globals: the allowed scratch mechanism)
static __device__ float g_Wall[256 * COUT];                  // [ci][co]
static __device__ float g_V  [(size_t)TOTPIX * 256];         // [pix][256]
static __device__ float g_PQK[(size_t)TOTPIX * 192];         // [pix][Pq0,Pq1,Pq2,Pk0,Pk1,Pk2 x32]
static __device__ float g_Q  [(size_t)TOTPIX * 32];
static __device__ float g_K  [(size_t)TOTPIX * 32];
static __device__ int   g_pix[TOTPIX];                       // addr of x[b,0,h,w]
static __device__ float g_qsc[32], g_qof[32], g_ksc[32], g_kof[32];

// ---------------------------------------------------------------- prep kernels
__global__ void prep_wall(const float* __restrict__ Wq, const float* __restrict__ Wk,
                          const float* __restrict__ Wv) {
    int idx = blockIdx.x * 256 + threadIdx.x;
    if (idx >= 256 * COUT) return;
    int co = idx >> 8, ci = idx & 255;
    float v;
    if (co < 256)       v = Wv[co * 256 + ci];                               // 1x1 conv
    else if (co < 352) { int t = (co - 256) >> 5, c8 = (co - 256) & 31;
                         v = Wq[(c8 * 256 + ci) * 3 + t]; }                  // 1x3 taps
    else               { int t = (co - 352) >> 5, c8 = (co - 352) & 31;
                         v = Wk[(c8 * 256 + ci) * 3 + t]; }                  // 3x1 taps
    g_Wall[ci * COUT + co] = v;
}

__global__ void prep_bn(const float* bq, const float* qs, const float* qo, const float* qm, const float* qv,
                        const float* bk, const float* ks, const float* ko, const float* km, const float* kv) {
    int c = threadIdx.x;
    if (c >= 32) return;
    float sc = qs[c] * rsqrtf(qv[c] + 1e-5f);
    g_qsc[c] = sc;
    g_qof[c] = bq[c] * sc + qo[c] - qm[c] * sc;
    sc = ks[c] * rsqrtf(kv[c] + 1e-5f);
    g_ksc[c] = sc;
    g_kof[c] = bk[c] * sc + ko[c] - km[c] * sc;
}

__global__ void prep_pix() {
    int inst = blockIdx.y;
    int region = inst >> 3, b = inst & 7;
    int N = c_N[region];
    int n = blockIdx.x * 256 + threadIdx.x;
    if (n >= N) return;
    int Wr = c_Wr[region];
    int h = n / Wr, w = n - h * Wr;
    g_pix[c_base[region] + b * N + n] = b * (256 * HW) + (c_h0[region] + h) * IMG + c_w0[region] + w;
}

__global__ void copy_x(const float4* __restrict__ x, float4* __restrict__ o) {
    int i = blockIdx.x * blockDim.x + threadIdx.x;
    int stride = gridDim.x * blockDim.x;
    for (; i < 8388608; i += stride) o[i] = x[i];   // 8*256*128*128/4
}

// ------------------------------------------------- QKV GEMM: [pix,256]@[256,448]
__global__ __launch_bounds__(128) void qkv_gemm(const float* __restrict__ x,
                                                const float* __restrict__ bv) {
    int inst = blockIdx.z;
    int region = inst >> 3, b = inst & 7;
    int N = c_N[region];
    int m0 = blockIdx.y * 64;
    if (m0 >= N) return;
    int pb = c_base[region] + b * N;
    int n0 = blockIdx.x * 64;

    __shared__ float As[16][64];
    __shared__ float Bs[16][64];
    __shared__ int pas[64];
    int tid = threadIdx.x;
    if (tid < 64) pas[tid] = g_pix[pb + m0 + tid];
    __syncthreads();

    u64 acc[4][4];
#pragma unroll
    for (int i = 0; i < 4; i++)
#pragma unroll
        for (int jp = 0; jp < 4; jp++) acc[i][jp] = 0ull;

    int tm = tid & 15, tn2 = tid >> 4;       // tm: 4 rows, tn2: 8 cols (4 pairs)
    for (int k0 = 0; k0 < 256; k0 += 16) {
#pragma unroll
        for (int r = 0; r < 8; r++) {              // A: 64 pix x 16 ci
            int idx = tid + r * 128;
            int m = idx & 63, kk = idx >> 6;
            As[kk][m] = x[pas[m] + (k0 + kk) * HW];
        }
#pragma unroll
        for (int r = 0; r < 8; r++) {              // B: 16 ci x 64 co
            int idx = tid + r * 128;
            int n = idx & 63, kk = idx >> 6;
            Bs[kk][n] = g_Wall[(k0 + kk) * COUT + n0 + n];
        }
        __syncthreads();
#pragma unroll
        for (int kk = 0; kk < 16; kk++) {
            float4 a = *(float4*)&As[kk][tm * 4];
            double2 b0 = *(double2*)&Bs[kk][tn2 * 8];
            double2 b1 = *(double2*)&Bs[kk][tn2 * 8 + 4];
            u64 bw0 = d2u(b0.x), bw1 = d2u(b0.y), bw2 = d2u(b1.x), bw3 = d2u(b1.y);
            u64 a0 = dup2(a.x), a1 = dup2(a.y), a2 = dup2(a.z), a3 = dup2(a.w);
            acc[0][0] = ffma2(a0, bw0, acc[0][0]); acc[0][1] = ffma2(a0, bw1, acc[0][1]);
            acc[0][2] = ffma2(a0, bw2, acc[0][2]); acc[0][3] = ffma2(a0, bw3, acc[0][3]);
            acc[1][0] = ffma2(a1, bw0, acc[1][0]); acc[1][1] = ffma2(a1, bw1, acc[1][1]);
            acc[1][2] = ffma2(a1, bw2, acc[1][2]); acc[1][3] = ffma2(a1, bw3, acc[1][3]);
            acc[2][0] = ffma2(a2, bw0, acc[2][0]); acc[2][1] = ffma2(a2, bw1, acc[2][1]);
            acc[2][2] = ffma2(a2, bw2, acc[2][2]); acc[2][3] = ffma2(a2, bw3, acc[2][3]);
            acc[3][0] = ffma2(a3, bw0, acc[3][0]); acc[3][1] = ffma2(a3, bw1, acc[3][1]);
            acc[3][2] = ffma2(a3, bw2, acc[3][2]); acc[3][3] = ffma2(a3, bw3, acc[3][3]);
        }
        __syncthreads();
    }
#pragma unroll
    for (int i = 0; i < 4; i++) {
        size_t m = (size_t)(pb + m0 + tm * 4 + i);
#pragma unroll
        for (int jp = 0; jp < 4; jp++) {
            float2 v = u2f(acc[i][jp]);
            int co = n0 + tn2 * 8 + jp * 2;
            if (co < 256) {
                g_V[m * 256 + co]     = v.x + bv[co];
                g_V[m * 256 + co + 1] = v.y + bv[co + 1];
            } else {
                g_PQK[m * 192 + (co - 256)]     = v.x;
                g_PQK[m * 192 + (co - 256) + 1] = v.y;
            }
        }
    }
}

// ----------------------------- combine conv taps (window-local padding) + BN + ReLU
__global__ void combine_qk() {
    int inst = blockIdx.y;
    int region = inst >> 3, b = inst & 7;
    int N = c_N[region];
    int idx = blockIdx.x * 256 + threadIdx.x;
    int n = idx >> 5;
    if (n >= N) return;
    int c8 = idx & 31;
    int Wr = c_Wr[region], Hr = c_Hr[region];
    int pb = c_base[region] + b * N;
    int h = n / Wr, w = n - h * Wr;
    size_t rowp = (size_t)(pb + n) * 192;

    float q = g_PQK[rowp + 32 + c8];
    if (w > 0)      q += g_PQK[rowp - 192 + c8];
    if (w < Wr - 1) q += g_PQK[rowp + 192 + 64 + c8];
    g_Q[(size_t)(pb + n) * 32 + c8] = fmaxf(fmaf(q, g_qsc[c8], g_qof[c8]), 0.f);

    float k = g_PQK[rowp + 96 + 32 + c8];
    if (h > 0)      k += g_PQK[rowp - (size_t)Wr * 192 + 96 + c8];
    if (h < Hr - 1) k += g_PQK[rowp + (size_t)Wr * 192 + 96 + 64 + c8];
    g_K[(size_t)(pb + n) * 32 + c8] = fmaxf(fmaf(k, g_ksc[c8], g_kof[c8]), 0.f);
}

// ------------------------------------------- flash attention, d_qk=32, d_v=256
// Launched twice (win regions then shift regions): within a launch no two CTAs
// touch the same output pixel -> plain RMW stores, no atomics.
__global__ __launch_bounds__(256, 2) void attn(const float* __restrict__ gamma,
                                               float* __restrict__ out, int inst0) {
    int inst = inst0 + blockIdx.y;
    int region = inst >> 3, b = inst & 7;
    int N = c_N[region];
    int n0 = blockIdx.x * 32;
    if (n0 >= N) return;
    int pb = c_base[region] + b * N;

    __shared__ float Kt[32 * 32];     // [k][m] transposed: FFMA2 pairs contiguous in m
    __shared__ float Vs[32 * 256];
    __shared__ float Ps[32 * 33];
    __shared__ float rmax[32], rsum[32], rscale[32];
    __shared__ int pas[32];

    int tid = threadIdx.x;
    int lane = tid & 31, wrp = tid >> 5;
    if (tid < 32) {
        rmax[tid] = -1e30f; rsum[tid] = 0.f;
        pas[tid] = g_pix[pb + n0 + tid];
    }

    // per-thread Q row (row = lane) kept in registers for the whole kernel
    float q[32];
    {
        const float4* qp = (const float4*)&g_Q[(size_t)(pb + n0 + lane) * 32];
#pragma unroll
        for (int r = 0; r < 8; r++) {
            float4 t = qp[r];
            q[r * 4 + 0] = t.x; q[r * 4 + 1] = t.y; q[r * 4 + 2] = t.z; q[r * 4 + 3] = t.w;
        }
    }

    u64 acc[4][4];
#pragma unroll
    for (int i = 0; i < 4; i++)
#pragma unroll
        for (int jp = 0; jp < 4; jp++) acc[i][jp] = 0ull;

    int tn = tid & 7, tc = tid >> 3;   // PV/epilogue: rows tn+8i (coalesced stores), cols tc*8..+7

    int nmt = N >> 5;
    for (int mt = 0; mt < nmt; mt++) {
        int mb = pb + mt * 32;
        __syncthreads();
        {   // K tile, transposed into [k][m]
            int m = tid >> 3, k4 = tid & 7;
            float4 t = *(const float4*)&g_K[(size_t)(mb + m) * 32 + k4 * 4];
            Kt[(k4 * 4 + 0) * 32 + m] = t.x;
            Kt[(k4 * 4 + 1) * 32 + m] = t.y;
            Kt[(k4 * 4 + 2) * 32 + m] = t.z;
            Kt[(k4 * 4 + 3) * 32 + m] = t.w;
        }
#pragma unroll
        for (int r = 0; r < 8; r++) {
            int idx = tid + r * 256;
            int m = idx >> 6, c4 = idx & 63;
            *(float4*)&Vs[m * 256 + c4 * 4] = *(const float4*)&g_V[(size_t)(mb + m) * 256 + c4 * 4];
        }
        __syncthreads();
        {   // S[n=lane][m = wrp*4 .. +3] with FFMA2 over m-pairs
            u64 s01 = 0ull, s23 = 0ull;
#pragma unroll
            for (int k = 0; k < 32; k++) {
                u64 qq = dup2(q[k]);
                double2 kk = *(const double2*)&Kt[k * 32 + wrp * 4];
                s01 = ffma2(qq, d2u(kk.x), s01);
                s23 = ffma2(qq, d2u(kk.y), s23);
            }
            float2 a = u2f(s01), c = u2f(s23);
            Ps[lane * 33 + wrp * 4 + 0] = a.x;
            Ps[lane * 33 + wrp * 4 + 1] = a.y;
            Ps[lane * 33 + wrp * 4 + 2] = c.x;
            Ps[lane * 33 + wrp * 4 + 3] = c.y;
        }
        __syncthreads();
        {   // online softmax: 8 threads per row, 4 elems each
            int r = tid >> 3, qt = tid & 7;
            float* prow = &Ps[r * 33 + qt * 4];
            float p0 = prow[0], p1 = prow[1], p2 = prow[2], p3 = prow[3];
            float mx0 = rmax[r];
            float ml = fmaxf(fmaxf(p0, p1), fmaxf(p2, p3));
            ml = fmaxf(ml, __shfl_xor_sync(0xffffffffu, ml, 1));
            ml = fmaxf(ml, __shfl_xor_sync(0xffffffffu, ml, 2));
            ml = fmaxf(ml, __shfl_xor_sync(0xffffffffu, ml, 4));
            float nm = fmaxf(mx0, ml);
            p0 = __expf(p0 - nm); p1 = __expf(p1 - nm);
            p2 = __expf(p2 - nm); p3 = __expf(p3 - nm);
            prow[0] = p0; prow[1] = p1; prow[2] = p2; prow[3] = p3;
            float s = (p0 + p1) + (p2 + p3);
            s += __shfl_xor_sync(0xffffffffu, s, 1);
            s += __shfl_xor_sync(0xffffffffu, s, 2);
            s += __shfl_xor_sync(0xffffffffu, s, 4);
            if (qt == 0) {
                float sc = __expf(mx0 - nm);
                rsum[r] = rsum[r] * sc + s;
                rmax[r] = nm;
                rscale[r] = sc;
            }
        }
        __syncthreads();
#pragma unroll
        for (int i = 0; i < 4; i++) {      // rescale accumulators
            u64 sc2 = dup2(rscale[tn + 8 * i]);
#pragma unroll
            for (int jp = 0; jp < 4; jp++) acc[i][jp] = fmul2(sc2, acc[i][jp]);
        }
#pragma unroll
        for (int m = 0; m < 32; m++) {     // acc += P * V (FFMA2)
            double2 v0 = *(const double2*)&Vs[m * 256 + tc * 8];
            double2 v1 = *(const double2*)&Vs[m * 256 + tc * 8 + 4];
            u64 vv0 = d2u(v0.x), vv1 = d2u(v0.y), vv2 = d2u(v1.x), vv3 = d2u(v1.y);
#pragma unroll
            for (int i = 0; i < 4; i++) {
                u64 pp = dup2(Ps[(tn + 8 * i) * 33 + m]);
                acc[i][0] = ffma2(pp, vv0, acc[i][0]);
                acc[i][1] = ffma2(pp, vv1, acc[i][1]);
                acc[i][2] = ffma2(pp, vv2, acc[i][2]);
                acc[i][3] = ffma2(pp, vv3, acc[i][3]);
            }
        }
    }
    // epilogue: plain RMW (no atomics); lanes tn 0..7 -> consecutive pixels
    float g = 0.5f * gamma[0];
#pragma unroll
    for (int i = 0; i < 4; i++) {
        int n = tn + 8 * i;
        float f = g / rsum[n];
        u64 ff = dup2(f);
        int pa = pas[n];
#pragma unroll
        for (int jp = 0; jp < 4; jp++) {
            float2 r = u2f(fmul2(acc[i][jp], ff));
            int c = tc * 8 + jp * 2;
            out[pa + c * HW]       += r.x;
            out[pa + (c + 1) * HW] += r.y;
        }
    }
}

// ---------------------------------------------------------------- launcher
extern "C" void kernel_launch(void* const* d_in, const int* in_sizes, int n_in,
                              void* d_out, int out_size) {
    const float* x   = (const float*)d_in[0];
    const float* Wq  = (const float*)d_in[1];
    const float* bq  = (const float*)d_in[2];
    const float* q_s = (const float*)d_in[3];
    const float* q_o = (const float*)d_in[4];
    const float* q_m = (const float*)d_in[5];
    const float* q_v = (const float*)d_in[6];
    const float* Wk  = (const float*)d_in[7];
    const float* bk  = (const float*)d_in[8];
    const float* k_s = (const float*)d_in[9];
    const float* k_o = (const float*)d_in[10];
    const float* k_m = (const float*)d_in[11];
    const float* k_v = (const float*)d_in[12];
    const float* Wv  = (const float*)d_in[13];
    const float* bv  = (const float*)d_in[14];
    const float* gam = (const float*)d_in[15];
    float* out = (float*)d_out;

    prep_wall<<<448, 256>>>(Wq, Wk, Wv);
    prep_bn<<<1, 32>>>(bq, q_s, q_o, q_m, q_v, bk, k_s, k_o, k_m, k_v);
    prep_pix<<<dim3(6, 232), 256>>>();
    copy_x<<<4096, 256>>>((const float4*)x, (float4*)out);
    qkv_gemm<<<dim3(7, 24, 232), 128>>>(x, bv);
    combine_qk<<<dim3(192, 232), 256>>>();
    // win regions (0..11): pixels disjoint within launch -> plain RMW
    attn<<<dim3(32, 96), 256>>>(gam, out, 0);
    // shift regions (12..28): partition of the image -> plain RMW
    attn<<<dim3(48, 136), 256>>>(gam, out, 96);
}

// round 6
// speedup vs baseline: 1.4110x; 1.3546x over previous
#include <cuda_runtime.h>
#include <math.h>
#include <stdint.h>

// Problem constants (B=8, C=256, H=W=128, win_n=4, shift=16)
#define HW   16384      // 128*128
#define IMG  128
#define NREG 29
#define TOTPIX 229376   // sum over regions of N * 8 batches
#define COUT 448        // 256 V + 96 Pq(3 taps x 32) + 96 Pk

typedef unsigned long long u64;
typedef uint32_t u32;

// ---- packed fp32x2 helpers (used in qkv gemm) ----
__device__ __forceinline__ u64 ffma2(u64 a, u64 b, u64 c) {
    u64 d; asm("fma.rn.f32x2 %0, %1, %2, %3;" : "=l"(d) : "l"(a), "l"(b), "l"(c)); return d;
}
__device__ __forceinline__ u64 dup2(float x) {
    u64 u; asm("mov.b64 %0, {%1,%1};" : "=l"(u) : "f"(x)); return u;
}
__device__ __forceinline__ float2 u2f(u64 u) {
    float2 f; asm("mov.b64 {%0,%1}, %2;" : "=f"(f.x), "=f"(f.y) : "l"(u)); return f;
}
__device__ __forceinline__ u64 d2u(double x) { return (u64)__double_as_longlong(x); }

// tf32 round-to-nearest (value stays in fp32 container, low mantissa zeroed)
__device__ __forceinline__ float tf32r(float x) {
    u32 u; asm("cvt.rna.tf32.f32 %0, %1;" : "=r"(u) : "f"(x));
    return __uint_as_float(u);
}

// m16n8k8 tf32 MMA, fp32 accumulate
#define MMA_TF32(d, a0, a1, a2, a3, b0, b1)                                          \
    asm volatile("mma.sync.aligned.m16n8k8.row.col.f32.tf32.tf32.f32 "               \
                 "{%0,%1,%2,%3},{%4,%5,%6,%7},{%8,%9},{%0,%1,%2,%3};"                \
                 : "+f"(d[0]), "+f"(d[1]), "+f"(d[2]), "+f"(d[3])                    \
                 : "r"(a0), "r"(a1), "r"(a2), "r"(a3), "r"(b0), "r"(b1))

// Region tables: 12 win (rows 1..3 x cols 0..3), 9 shift-inner, 8 borders
__constant__ int c_h0[NREG] = {32,32,32,32, 64,64,64,64, 96,96,96,96,
                               16,16,16, 48,48,48, 80,80,80,
                               0,0,0, 16,16, 112,112,112};
__constant__ int c_w0[NREG] = {0,32,64,96, 0,32,64,96, 0,32,64,96,
                               16,48,80, 16,48,80, 16,48,80,
                               0,16,112, 0,112, 0,16,112};
__constant__ int c_Hr[NREG] = {32,32,32,32,32,32,32,32,32,32,32,32,
                               32,32,32,32,32,32,32,32,32,
                               16,16,16, 96,96, 16,16,16};
__constant__ int c_Wr[NREG] = {32,32,32,32,32,32,32,32,32,32,32,32,
                               32,32,32,32,32,32,32,32,32,
                               16,96,16, 16,16, 16,96,16};
__constant__ int c_N[NREG]  = {1024,1024,1024,1024,1024,1024,1024,1024,1024,1024,1024,1024,
                               1024,1024,1024,1024,1024,1024,1024,1024,1024,
                               256,1536,256, 1536,1536, 256,1536,256};
__constant__ int c_base[NREG] = {0,8192,16384,24576,32768,40960,49152,57344,65536,73728,81920,90112,
                                 98304,106496,114688,122880,131072,139264,147456,155648,163840,
                                 172032,174080,186368, 188416,200704, 212992,215040,227328};

// Scratch (__device__ globals)
static __device__ float g_Wall[256 * COUT];                  // [ci][co]
static __device__ float g_V  [(size_t)TOTPIX * 256];         // [pix][256], tf32-rounded
static __device__ float g_PQK[(size_t)TOTPIX * 192];         // [pix][Pq0,Pq1,Pq2,Pk0,Pk1,Pk2 x32]
static __device__ float g_Qh [(size_t)TOTPIX * 32];          // tf32 hi
static __device__ float g_Ql [(size_t)TOTPIX * 32];          // tf32 lo (residual)
static __device__ float g_Kh [(size_t)TOTPIX * 32];
static __device__ float g_Kl [(size_t)TOTPIX * 32];
static __device__ int   g_pix[TOTPIX];                       // addr of x[b,0,h,w]
static __device__ float g_qsc[32], g_qof[32], g_ksc[32], g_kof[32];

// ---------------------------------------------------------------- prep kernels
__global__ void prep_wall(const float* __restrict__ Wq, const float* __restrict__ Wk,
                          const float* __restrict__ Wv) {
    int idx = blockIdx.x * 256 + threadIdx.x;
    if (idx >= 256 * COUT) return;
    int co = idx >> 8, ci = idx & 255;
    float v;
    if (co < 256)       v = Wv[co * 256 + ci];
    else if (co < 352) { int t = (co - 256) >> 5, c8 = (co - 256) & 31;
                         v = Wq[(c8 * 256 + ci) * 3 + t]; }
    else               { int t = (co - 352) >> 5, c8 = (co - 352) & 31;
                         v = Wk[(c8 * 256 + ci) * 3 + t]; }
    g_Wall[ci * COUT + co] = v;
}

__global__ void prep_bn(const float* bq, const float* qs, const float* qo, const float* qm, const float* qv,
                        const float* bk, const float* ks, const float* ko, const float* km, const float* kv) {
    int c = threadIdx.x;
    if (c >= 32) return;
    float sc = qs[c] * rsqrtf(qv[c] + 1e-5f);
    g_qsc[c] = sc;
    g_qof[c] = bq[c] * sc + qo[c] - qm[c] * sc;
    sc = ks[c] * rsqrtf(kv[c] + 1e-5f);
    g_ksc[c] = sc;
    g_kof[c] = bk[c] * sc + ko[c] - km[c] * sc;
}

__global__ void prep_pix() {
    int inst = blockIdx.y;
    int region = inst >> 3, b = inst & 7;
    int N = c_N[region];
    int n = blockIdx.x * 256 + threadIdx.x;
    if (n >= N) return;
    int Wr = c_Wr[region];
    int h = n / Wr, w = n - h * Wr;
    g_pix[c_base[region] + b * N + n] = b * (256 * HW) + (c_h0[region] + h) * IMG + c_w0[region] + w;
}

__global__ void copy_x(const float4* __restrict__ x, float4* __restrict__ o) {
    int i = blockIdx.x * blockDim.x + threadIdx.x;
    int stride = gridDim.x * blockDim.x;
    for (; i < 8388608; i += stride) o[i] = x[i];
}

// ------------------------------------------------- QKV GEMM: [pix,256]@[256,448]
__global__ __launch_bounds__(128) void qkv_gemm(const float* __restrict__ x,
                                                const float* __restrict__ bv) {
    int inst = blockIdx.z;
    int region = inst >> 3, b = inst & 7;
    int N = c_N[region];
    int m0 = blockIdx.y * 64;
    if (m0 >= N) return;
    int pb = c_base[region] + b * N;
    int n0 = blockIdx.x * 64;

    __shared__ float As[16][64];
    __shared__ float Bs[16][64];
    __shared__ int pas[64];
    int tid = threadIdx.x;
    if (tid < 64) pas[tid] = g_pix[pb + m0 + tid];
    __syncthreads();

    u64 acc[4][4];
#pragma unroll
    for (int i = 0; i < 4; i++)
#pragma unroll
        for (int jp = 0; jp < 4; jp++) acc[i][jp] = 0ull;

    int tm = tid & 15, tn2 = tid >> 4;
    for (int k0 = 0; k0 < 256; k0 += 16) {
#pragma unroll
        for (int r = 0; r < 8; r++) {
            int idx = tid + r * 128;
            int m = idx & 63, kk = idx >> 6;
            As[kk][m] = x[pas[m] + (k0 + kk) * HW];
        }
#pragma unroll
        for (int r = 0; r < 8; r++) {
            int idx = tid + r * 128;
            int n = idx & 63, kk = idx >> 6;
            Bs[kk][n] = g_Wall[(k0 + kk) * COUT + n0 + n];
        }
        __syncthreads();
#pragma unroll
        for (int kk = 0; kk < 16; kk++) {
            float4 a = *(float4*)&As[kk][tm * 4];
            double2 b0 = *(double2*)&Bs[kk][tn2 * 8];
            double2 b1 = *(double2*)&Bs[kk][tn2 * 8 + 4];
            u64 bw0 = d2u(b0.x), bw1 = d2u(b0.y), bw2 = d2u(b1.x), bw3 = d2u(b1.y);
            u64 a0 = dup2(a.x), a1 = dup2(a.y), a2 = dup2(a.z), a3 = dup2(a.w);
            acc[0][0] = ffma2(a0, bw0, acc[0][0]); acc[0][1] = ffma2(a0, bw1, acc[0][1]);
            acc[0][2] = ffma2(a0, bw2, acc[0][2]); acc[0][3] = ffma2(a0, bw3, acc[0][3]);
            acc[1][0] = ffma2(a1, bw0, acc[1][0]); acc[1][1] = ffma2(a1, bw1, acc[1][1]);
            acc[1][2] = ffma2(a1, bw2, acc[1][2]); acc[1][3] = ffma2(a1, bw3, acc[1][3]);
            acc[2][0] = ffma2(a2, bw0, acc[2][0]); acc[2][1] = ffma2(a2, bw1, acc[2][1]);
            acc[2][2] = ffma2(a2, bw2, acc[2][2]); acc[2][3] = ffma2(a2, bw3, acc[2][3]);
            acc[3][0] = ffma2(a3, bw0, acc[3][0]); acc[3][1] = ffma2(a3, bw1, acc[3][1]);
            acc[3][2] = ffma2(a3, bw2, acc[3][2]); acc[3][3] = ffma2(a3, bw3, acc[3][3]);
        }
        __syncthreads();
    }
#pragma unroll
    for (int i = 0; i < 4; i++) {
        size_t m = (size_t)(pb + m0 + tm * 4 + i);
#pragma unroll
        for (int jp = 0; jp < 4; jp++) {
            float2 v = u2f(acc[i][jp]);
            int co = n0 + tn2 * 8 + jp * 2;
            if (co < 256) {
                // V is consumed by the tf32 PV MMA: pre-round once here
                g_V[m * 256 + co]     = tf32r(v.x + bv[co]);
                g_V[m * 256 + co + 1] = tf32r(v.y + bv[co + 1]);
            } else {
                g_PQK[m * 192 + (co - 256)]     = v.x;
                g_PQK[m * 192 + (co - 256) + 1] = v.y;
            }
        }
    }
}

// ------------- combine conv taps + BN + ReLU, split Q/K into tf32 hi/lo pairs
__global__ void combine_qk() {
    int inst = blockIdx.y;
    int region = inst >> 3, b = inst & 7;
    int N = c_N[region];
    int idx = blockIdx.x * 256 + threadIdx.x;
    int n = idx >> 5;
    if (n >= N) return;
    int c8 = idx & 31;
    int Wr = c_Wr[region], Hr = c_Hr[region];
    int pb = c_base[region] + b * N;
    int h = n / Wr, w = n - h * Wr;
    size_t rowp = (size_t)(pb + n) * 192;

    float q = g_PQK[rowp + 32 + c8];
    if (w > 0)      q += g_PQK[rowp - 192 + c8];
    if (w < Wr - 1) q += g_PQK[rowp + 192 + 64 + c8];
    q = fmaxf(fmaf(q, g_qsc[c8], g_qof[c8]), 0.f);
    float qh = tf32r(q);
    g_Qh[(size_t)(pb + n) * 32 + c8] = qh;
    g_Ql[(size_t)(pb + n) * 32 + c8] = tf32r(q - qh);

    float k = g_PQK[rowp + 96 + 32 + c8];
    if (h > 0)      k += g_PQK[rowp - (size_t)Wr * 192 + 96 + c8];
    if (h < Hr - 1) k += g_PQK[rowp + (size_t)Wr * 192 + 96 + 64 + c8];
    k = fmaxf(fmaf(k, g_ksc[c8], g_kof[c8]), 0.f);
    float kh = tf32r(k);
    g_Kh[(size_t)(pb + n) * 32 + c8] = kh;
    g_Kl[(size_t)(pb + n) * 32 + c8] = tf32r(k - kh);
}

// ------------------------------------------- tensor-core flash attention
// S = split-tf32 (3 MMA, ~fp32 precision, protects softmax); PV = tf32.
// Launched twice (win / shift): no output overlap within a launch -> plain RMW.
__global__ __launch_bounds__(256, 2) void attn(const float* __restrict__ gamma,
                                               float* __restrict__ out, int inst0) {
    int inst = inst0 + blockIdx.y;
    int region = inst >> 3, b = inst & 7;
    int N = c_N[region];
    int n0 = blockIdx.x * 32;
    if (n0 >= N) return;
    int pb = c_base[region] + b * N;

    __shared__ float Ksh[32 * 36];
    __shared__ float Ksl[32 * 36];
    __shared__ float Vs [32 * 264];
    __shared__ float Ps [32 * 33];
    __shared__ float rmax[32], rsum[32], rscale[32];
    __shared__ int pas[32];

    int tid = threadIdx.x;
    int lane = tid & 31, w = tid >> 5;
    int g = lane >> 2, t = lane & 3;
    if (tid < 32) {
        rmax[tid] = -1e30f; rsum[tid] = 0.f;
        pas[tid] = g_pix[pb + n0 + tid];
    }

    // S-GEMM warp mapping: warp -> (q-row tile smt of 2, key tile snt of 4)
    int smt = w >> 2, snt = w & 3;
    // Preload Q fragments (hi/lo) for this warp's 16 q-rows; fixed all kernel.
    u32 aqh[4][4], aql[4][4];
    {
        size_t r0 = (size_t)(pb + n0 + smt * 16 + g) * 32;
        size_t r8 = (size_t)(pb + n0 + smt * 16 + g + 8) * 32;
#pragma unroll
        for (int kt = 0; kt < 4; kt++) {
            int c0 = kt * 8 + t, c4 = c0 + 4;
            aqh[kt][0] = __float_as_uint(g_Qh[r0 + c0]);
            aqh[kt][1] = __float_as_uint(g_Qh[r8 + c0]);
            aqh[kt][2] = __float_as_uint(g_Qh[r0 + c4]);
            aqh[kt][3] = __float_as_uint(g_Qh[r8 + c4]);
            aql[kt][0] = __float_as_uint(g_Ql[r0 + c0]);
            aql[kt][1] = __float_as_uint(g_Ql[r8 + c0]);
            aql[kt][2] = __float_as_uint(g_Ql[r0 + c4]);
            aql[kt][3] = __float_as_uint(g_Ql[r8 + c4]);
        }
    }

    // PV warp mapping: warp -> (q-row tile wm of 2, 64-channel slab)
    int wm = w & 1, wch = (w >> 1) * 64;
    float acc[8][4];
#pragma unroll
    for (int nt = 0; nt < 8; nt++)
#pragma unroll
        for (int r = 0; r < 4; r++) acc[nt][r] = 0.f;

    int nmt = N >> 5;
    for (int mt = 0; mt < nmt; mt++) {
        int mb = pb + mt * 32;
        __syncthreads();
        {   // K tile hi/lo: 32 keys x 32 dims each
            int m = tid >> 3, c4 = tid & 7;
            *(float4*)&Ksh[m * 36 + c4 * 4] = *(const float4*)&g_Kh[(size_t)(mb + m) * 32 + c4 * 4];
            *(float4*)&Ksl[m * 36 + c4 * 4] = *(const float4*)&g_Kl[(size_t)(mb + m) * 32 + c4 * 4];
        }
#pragma unroll
        for (int r = 0; r < 8; r++) {   // V tile: 32 keys x 256 ch (stride 264)
            int idx = tid + r * 256;
            int m = idx >> 6, c4 = idx & 63;
            *(float4*)&Vs[m * 264 + c4 * 4] = *(const float4*)&g_V[(size_t)(mb + m) * 256 + c4 * 4];
        }
        __syncthreads();
        {   // S: split-tf32, D[16 rows x 8 keys] per warp
            float sacc[4] = {0.f, 0.f, 0.f, 0.f};
#pragma unroll
            for (int kt = 0; kt < 4; kt++) {
                int kr = (snt * 8 + g) * 36 + kt * 8 + t;
                u32 bh0 = __float_as_uint(Ksh[kr]);
                u32 bh1 = __float_as_uint(Ksh[kr + 4]);
                u32 bl0 = __float_as_uint(Ksl[kr]);
                u32 bl1 = __float_as_uint(Ksl[kr + 4]);
                MMA_TF32(sacc, aqh[kt][0], aqh[kt][1], aqh[kt][2], aqh[kt][3], bh0, bh1);
                MMA_TF32(sacc, aqh[kt][0], aqh[kt][1], aqh[kt][2], aqh[kt][3], bl0, bl1);
                MMA_TF32(sacc, aql[kt][0], aql[kt][1], aql[kt][2], aql[kt][3], bh0, bh1);
            }
            int pr0 = (smt * 16 + g) * 33 + snt * 8 + 2 * t;
            int pr8 = (smt * 16 + g + 8) * 33 + snt * 8 + 2 * t;
            Ps[pr0]     = sacc[0];
            Ps[pr0 + 1] = sacc[1];
            Ps[pr8]     = sacc[2];
            Ps[pr8 + 1] = sacc[3];
        }
        __syncthreads();
        {   // online softmax: 8 threads per row, 4 elems each; store tf32-rounded P
            int r = tid >> 3, qt = tid & 7;
            float* prow = &Ps[r * 33 + qt * 4];
            float p0 = prow[0], p1 = prow[1], p2 = prow[2], p3 = prow[3];
            float mx0 = rmax[r];
            float ml = fmaxf(fmaxf(p0, p1), fmaxf(p2, p3));
            ml = fmaxf(ml, __shfl_xor_sync(0xffffffffu, ml, 1));
            ml = fmaxf(ml, __shfl_xor_sync(0xffffffffu, ml, 2));
            ml = fmaxf(ml, __shfl_xor_sync(0xffffffffu, ml, 4));
            float nm = fmaxf(mx0, ml);
            p0 = __expf(p0 - nm); p1 = __expf(p1 - nm);
            p2 = __expf(p2 - nm); p3 = __expf(p3 - nm);
            prow[0] = tf32r(p0); prow[1] = tf32r(p1);
            prow[2] = tf32r(p2); prow[3] = tf32r(p3);
            float s = (p0 + p1) + (p2 + p3);
            s += __shfl_xor_sync(0xffffffffu, s, 1);
            s += __shfl_xor_sync(0xffffffffu, s, 2);
            s += __shfl_xor_sync(0xffffffffu, s, 4);
            if (qt == 0) {
                float sc = __expf(mx0 - nm);
                rsum[r] = rsum[r] * sc + s;
                rmax[r] = nm;
                rscale[r] = sc;
            }
        }
        __syncthreads();
        {   // rescale + PV tf32 MMA
            float sc0 = rscale[wm * 16 + g];
            float sc1 = rscale[wm * 16 + g + 8];
#pragma unroll
            for (int nt = 0; nt < 8; nt++) {
                acc[nt][0] *= sc0; acc[nt][1] *= sc0;
                acc[nt][2] *= sc1; acc[nt][3] *= sc1;
            }
#pragma unroll
            for (int kt = 0; kt < 4; kt++) {
                int pr0 = (wm * 16 + g) * 33 + kt * 8 + t;
                int pr8 = (wm * 16 + g + 8) * 33 + kt * 8 + t;
                u32 pa0 = __float_as_uint(Ps[pr0]);
                u32 pa1 = __float_as_uint(Ps[pr8]);
                u32 pa2 = __float_as_uint(Ps[pr0 + 4]);
                u32 pa3 = __float_as_uint(Ps[pr8 + 4]);
                int v0r = (kt * 8 + t) * 264 + wch;
                int v1r = (kt * 8 + t + 4) * 264 + wch;
#pragma unroll
                for (int nt = 0; nt < 8; nt++) {
                    u32 b0 = __float_as_uint(Vs[v0r + nt * 8 + g]);
                    u32 b1 = __float_as_uint(Vs[v1r + nt * 8 + g]);
                    MMA_TF32(acc[nt], pa0, pa1, pa2, pa3, b0, b1);
                }
            }
        }
    }
    __syncthreads();
    // stage normalized output into Vs (reuse), then coalesced RMW
    {
        float gm = 0.5f * gamma[0];
        float f0 = gm / rsum[wm * 16 + g];
        float f1 = gm / rsum[wm * 16 + g + 8];
        int r0 = (wm * 16 + g) * 264 + wch + 2 * t;
        int r8 = (wm * 16 + g + 8) * 264 + wch + 2 * t;
#pragma unroll
        for (int nt = 0; nt < 8; nt++) {
            Vs[r0 + nt * 8]     = acc[nt][0] * f0;
            Vs[r0 + nt * 8 + 1] = acc[nt][1] * f0;
            Vs[r8 + nt * 8]     = acc[nt][2] * f1;
            Vs[r8 + nt * 8 + 1] = acc[nt][3] * f1;
        }
    }
    __syncthreads();
    {
        int tn = tid & 7, tc = tid >> 3;
#pragma unroll
        for (int i = 0; i < 4; i++) {
            int row = tn + 8 * i;
            int pa = pas[row];
#pragma unroll
            for (int j = 0; j < 8; j++) {
                int c = tc * 8 + j;
                out[pa + c * HW] += Vs[row * 264 + c];
            }
        }
    }
}

// ---------------------------------------------------------------- launcher
extern "C" void kernel_launch(void* const* d_in, const int* in_sizes, int n_in,
                              void* d_out, int out_size) {
    const float* x   = (const float*)d_in[0];
    const float* Wq  = (const float*)d_in[1];
    const float* bq  = (const float*)d_in[2];
    const float* q_s = (const float*)d_in[3];
    const float* q_o = (const float*)d_in[4];
    const float* q_m = (const float*)d_in[5];
    const float* q_v = (const float*)d_in[6];
    const float* Wk  = (const float*)d_in[7];
    const float* bk  = (const float*)d_in[8];
    const float* k_s = (const float*)d_in[9];
    const float* k_o = (const float*)d_in[10];
    const float* k_m = (const float*)d_in[11];
    const float* k_v = (const float*)d_in[12];
    const float* Wv  = (const float*)d_in[13];
    const float* bv  = (const float*)d_in[14];
    const float* gam = (const float*)d_in[15];
    float* out = (float*)d_out;

    prep_wall<<<448, 256>>>(Wq, Wk, Wv);
    prep_bn<<<1, 32>>>(bq, q_s, q_o, q_m, q_v, bk, k_s, k_o, k_m, k_v);
    prep_pix<<<dim3(6, 232), 256>>>();
    copy_x<<<4096, 256>>>((const float4*)x, (float4*)out);
    qkv_gemm<<<dim3(7, 24, 232), 128>>>(x, bv);
    combine_qk<<<dim3(192, 232), 256>>>();
    // win regions (0..11): disjoint pixels within launch -> plain RMW
    attn<<<dim3(32, 96), 256>>>(gam, out, 0);
    // shift regions (12..28): partition of image -> plain RMW
    attn<<<dim3(48, 136), 256>>>(gam, out, 96);
}

// round 7
// speedup vs baseline: 1.5093x; 1.0696x over previous
#include <cuda_runtime.h>
#include <math.h>
#include <stdint.h>

// Problem constants (B=8, C=256, H=W=128, win_n=4, shift=16)
#define HW   16384
#define IMG  128
#define NREG 29
#define TOTPIX 229376
#define COUT 448        // 256 V + 96 Pq(3 taps x 32) + 96 Pk

typedef uint32_t u32;

// tf32 round-to-nearest (fp32 container, low mantissa zeroed)
__device__ __forceinline__ float tf32r(float x) {
    u32 u; asm("cvt.rna.tf32.f32 %0, %1;" : "=r"(u) : "f"(x));
    return __uint_as_float(u);
}

// m16n8k8 tf32 MMA, fp32 accumulate
#define MMA_TF32(d, a0, a1, a2, a3, b0, b1)                                          \
    asm volatile("mma.sync.aligned.m16n8k8.row.col.f32.tf32.tf32.f32 "               \
                 "{%0,%1,%2,%3},{%4,%5,%6,%7},{%8,%9},{%0,%1,%2,%3};"                \
                 : "+f"(d[0]), "+f"(d[1]), "+f"(d[2]), "+f"(d[3])                    \
                 : "r"(a0), "r"(a1), "r"(a2), "r"(a3), "r"(b0), "r"(b1))

// Region tables: 12 win (rows 1..3 x cols 0..3), 9 shift-inner, 8 borders
__constant__ int c_h0[NREG] = {32,32,32,32, 64,64,64,64, 96,96,96,96,
                               16,16,16, 48,48,48, 80,80,80,
                               0,0,0, 16,16, 112,112,112};
__constant__ int c_w0[NREG] = {0,32,64,96, 0,32,64,96, 0,32,64,96,
                               16,48,80, 16,48,80, 16,48,80,
                               0,16,112, 0,112, 0,16,112};
__constant__ int c_Hr[NREG] = {32,32,32,32,32,32,32,32,32,32,32,32,
                               32,32,32,32,32,32,32,32,32,
                               16,16,16, 96,96, 16,16,16};
__constant__ int c_Wr[NREG] = {32,32,32,32,32,32,32,32,32,32,32,32,
                               32,32,32,32,32,32,32,32,32,
                               16,96,16, 16,16, 16,96,16};
__constant__ int c_N[NREG]  = {1024,1024,1024,1024,1024,1024,1024,1024,1024,1024,1024,1024,
                               1024,1024,1024,1024,1024,1024,1024,1024,1024,
                               256,1536,256, 1536,1536, 256,1536,256};
__constant__ int c_base[NREG] = {0,8192,16384,24576,32768,40960,49152,57344,65536,73728,81920,90112,
                                 98304,106496,114688,122880,131072,139264,147456,155648,163840,
                                 172032,174080,186368, 188416,200704, 212992,215040,227328};

// Scratch (__device__ globals)
static __device__ float g_Wh [COUT * 256];                   // [co][ci] tf32 hi
static __device__ float g_Wl [COUT * 256];                   // [co][ci] tf32 lo
static __device__ float g_V  [(size_t)TOTPIX * 256];         // [pix][256], tf32-rounded
static __device__ float g_PQK[(size_t)TOTPIX * 192];
static __device__ float g_Qh [(size_t)TOTPIX * 32];
static __device__ float g_Ql [(size_t)TOTPIX * 32];
static __device__ float g_Kh [(size_t)TOTPIX * 32];
static __device__ float g_Kl [(size_t)TOTPIX * 32];
static __device__ int   g_pix[TOTPIX];
static __device__ float g_qsc[32], g_qof[32], g_ksc[32], g_kof[32];

// ---------------------------------------------------------------- prep kernels
__global__ void prep_wall(const float* __restrict__ Wq, const float* __restrict__ Wk,
                          const float* __restrict__ Wv) {
    int idx = blockIdx.x * 256 + threadIdx.x;
    if (idx >= 256 * COUT) return;
    int co = idx >> 8, ci = idx & 255;
    float v;
    if (co < 256)       v = Wv[co * 256 + ci];
    else if (co < 352) { int t = (co - 256) >> 5, c8 = (co - 256) & 31;
                         v = Wq[(c8 * 256 + ci) * 3 + t]; }
    else               { int t = (co - 352) >> 5, c8 = (co - 352) & 31;
                         v = Wk[(c8 * 256 + ci) * 3 + t]; }
    float h = tf32r(v);
    g_Wh[co * 256 + ci] = h;
    g_Wl[co * 256 + ci] = tf32r(v - h);
}

__global__ void prep_bn(const float* bq, const float* qs, const float* qo, const float* qm, const float* qv,
                        const float* bk, const float* ks, const float* ko, const float* km, const float* kv) {
    int c = threadIdx.x;
    if (c >= 32) return;
    float sc = qs[c] * rsqrtf(qv[c] + 1e-5f);
    g_qsc[c] = sc;
    g_qof[c] = bq[c] * sc + qo[c] - qm[c] * sc;
    sc = ks[c] * rsqrtf(kv[c] + 1e-5f);
    g_ksc[c] = sc;
    g_kof[c] = bk[c] * sc + ko[c] - km[c] * sc;
}

__global__ void prep_pix() {
    int inst = blockIdx.y;
    int region = inst >> 3, b = inst & 7;
    int N = c_N[region];
    int n = blockIdx.x * 256 + threadIdx.x;
    if (n >= N) return;
    int Wr = c_Wr[region];
    int h = n / Wr, w = n - h * Wr;
    g_pix[c_base[region] + b * N + n] = b * (256 * HW) + (c_h0[region] + h) * IMG + c_w0[region] + w;
}

__global__ void copy_x(const float4* __restrict__ x, float4* __restrict__ o) {
    int i = blockIdx.x * blockDim.x + threadIdx.x;
    int stride = gridDim.x * blockDim.x;
    for (; i < 8388608; i += stride) o[i] = x[i];
}

// ---------------- QKV GEMM: [pix,256]@[256,448], split-tf32 MMA (~fp32 accurate)
__global__ __launch_bounds__(256) void qkv_gemm(const float* __restrict__ x,
                                                const float* __restrict__ bv) {
    int inst = blockIdx.z;
    int region = inst >> 3, b = inst & 7;
    int N = c_N[region];
    int m0 = blockIdx.y * 64;
    if (m0 >= N) return;
    int pb = c_base[region] + b * N;
    int n0 = blockIdx.x * 64;

    __shared__ float Ash[64 * 33], Asl[64 * 33];   // [m][k], stride 33: conflict-free
    __shared__ float Bsh[64 * 36], Bsl[64 * 36];   // [n][k], stride 36: float4-friendly
    __shared__ int pas[64];

    int tid = threadIdx.x;
    if (tid < 64) pas[tid] = g_pix[pb + m0 + tid];
    __syncthreads();

    int lane = tid & 31, w = tid >> 5;
    int g = lane >> 2, t = lane & 3;
    int mt = w & 3, ntq = w >> 2;                  // rows mt*16, cols ntq*32

    float acc[4][4];
#pragma unroll
    for (int i = 0; i < 4; i++)
#pragma unroll
        for (int j = 0; j < 4; j++) acc[i][j] = 0.f;

    for (int k0 = 0; k0 < 256; k0 += 32) {
        __syncthreads();
#pragma unroll
        for (int r = 0; r < 8; r++) {              // A gather: 64 m x 32 k
            int idx = tid + r * 256;
            int m = idx & 63, kk = idx >> 6;
            float v = x[pas[m] + (k0 + kk) * HW];
            float h = tf32r(v);
            Ash[m * 33 + kk] = h;
            Asl[m * 33 + kk] = tf32r(v - h);
        }
#pragma unroll
        for (int r = 0; r < 2; r++) {              // B: 64 n x 32 k (float4)
            int idx = tid + r * 256;
            int n = idx >> 3, c4 = idx & 7;
            *(float4*)&Bsh[n * 36 + c4 * 4] = *(const float4*)&g_Wh[(n0 + n) * 256 + k0 + c4 * 4];
            *(float4*)&Bsl[n * 36 + c4 * 4] = *(const float4*)&g_Wl[(n0 + n) * 256 + k0 + c4 * 4];
        }
        __syncthreads();
#pragma unroll
        for (int kt = 0; kt < 4; kt++) {
            int ar = (mt * 16 + g) * 33 + kt * 8 + t;
            int ar8 = ar + 8 * 33;
            u32 ah0 = __float_as_uint(Ash[ar]);
            u32 ah1 = __float_as_uint(Ash[ar8]);
            u32 ah2 = __float_as_uint(Ash[ar + 4]);
            u32 ah3 = __float_as_uint(Ash[ar8 + 4]);
            u32 al0 = __float_as_uint(Asl[ar]);
            u32 al1 = __float_as_uint(Asl[ar8]);
            u32 al2 = __float_as_uint(Asl[ar + 4]);
            u32 al3 = __float_as_uint(Asl[ar8 + 4]);
#pragma unroll
            for (int ns = 0; ns < 4; ns++) {
                int nr = (ntq * 32 + ns * 8 + g) * 36 + kt * 8 + t;
                u32 bh0 = __float_as_uint(Bsh[nr]);
                u32 bh1 = __float_as_uint(Bsh[nr + 4]);
                u32 bl0 = __float_as_uint(Bsl[nr]);
                u32 bl1 = __float_as_uint(Bsl[nr + 4]);
                MMA_TF32(acc[ns], ah0, ah1, ah2, ah3, bh0, bh1);
                MMA_TF32(acc[ns], al0, al1, al2, al3, bh0, bh1);
                MMA_TF32(acc[ns], ah0, ah1, ah2, ah3, bl0, bl1);
            }
        }
    }
    // epilogue: D[row g / g+8][2t, 2t+1] per ns
#pragma unroll
    for (int ns = 0; ns < 4; ns++) {
        int co = n0 + ntq * 32 + ns * 8 + 2 * t;
        size_t mg  = (size_t)(pb + m0 + mt * 16 + g);
        size_t mg8 = mg + 8;
        if (co < 256) {
            float b0 = bv[co], b1 = bv[co + 1];
            g_V[mg  * 256 + co]     = tf32r(acc[ns][0] + b0);
            g_V[mg  * 256 + co + 1] = tf32r(acc[ns][1] + b1);
            g_V[mg8 * 256 + co]     = tf32r(acc[ns][2] + b0);
            g_V[mg8 * 256 + co + 1] = tf32r(acc[ns][3] + b1);
        } else {
            int cp = co - 256;
            g_PQK[mg  * 192 + cp]     = acc[ns][0];
            g_PQK[mg  * 192 + cp + 1] = acc[ns][1];
            g_PQK[mg8 * 192 + cp]     = acc[ns][2];
            g_PQK[mg8 * 192 + cp + 1] = acc[ns][3];
        }
    }
}

// ------------- combine conv taps + BN + ReLU, split Q/K into tf32 hi/lo pairs
__global__ void combine_qk() {
    int inst = blockIdx.y;
    int region = inst >> 3, b = inst & 7;
    int N = c_N[region];
    int idx = blockIdx.x * 256 + threadIdx.x;
    int n = idx >> 5;
    if (n >= N) return;
    int c8 = idx & 31;
    int Wr = c_Wr[region], Hr = c_Hr[region];
    int pb = c_base[region] + b * N;
    int h = n / Wr, w = n - h * Wr;
    size_t rowp = (size_t)(pb + n) * 192;

    float q = g_PQK[rowp + 32 + c8];
    if (w > 0)      q += g_PQK[rowp - 192 + c8];
    if (w < Wr - 1) q += g_PQK[rowp + 192 + 64 + c8];
    q = fmaxf(fmaf(q, g_qsc[c8], g_qof[c8]), 0.f);
    float qh = tf32r(q);
    g_Qh[(size_t)(pb + n) * 32 + c8] = qh;
    g_Ql[(size_t)(pb + n) * 32 + c8] = tf32r(q - qh);

    float k = g_PQK[rowp + 96 + 32 + c8];
    if (h > 0)      k += g_PQK[rowp - (size_t)Wr * 192 + 96 + c8];
    if (h < Hr - 1) k += g_PQK[rowp + (size_t)Wr * 192 + 96 + 64 + c8];
    k = fmaxf(fmaf(k, g_ksc[c8], g_kof[c8]), 0.f);
    float kh = tf32r(k);
    g_Kh[(size_t)(pb + n) * 32 + c8] = kh;
    g_Kl[(size_t)(pb + n) * 32 + c8] = tf32r(k - kh);
}

// ------------------- tensor-core flash attention, 64 q-rows/CTA, 256 threads
// S = split-tf32 (protects softmax); PV = tf32. Two launches (win/shift): no
// output overlap within a launch -> plain RMW.
__global__ __launch_bounds__(256, 2) void attn(const float* __restrict__ gamma,
                                               float* __restrict__ out, int inst0) {
    extern __shared__ float sm[];
    float* Qsh = sm;                       // 64*36
    float* Qsl = Qsh + 64 * 36;            // 64*36
    float* Ksh = Qsl + 64 * 36;            // 32*36
    float* Ksl = Ksh + 32 * 36;            // 32*36
    float* Vs  = Ksl + 32 * 36;            // 32*264
    float* Ps  = Vs + 32 * 264;            // 64*33
    float* rmax = Ps + 64 * 33;
    float* rsum = rmax + 64;
    float* rscale = rsum + 64;
    int*   pas = (int*)(rscale + 64);      // 64

    int inst = inst0 + blockIdx.y;
    int region = inst >> 3, b = inst & 7;
    int N = c_N[region];
    int n0 = blockIdx.x * 64;
    if (n0 >= N) return;
    int pb = c_base[region] + b * N;

    int tid = threadIdx.x;
    int lane = tid & 31, w = tid >> 5;
    int g = lane >> 2, t = lane & 3;
    if (tid < 64) {
        rmax[tid] = -1e30f; rsum[tid] = 0.f;
        pas[tid] = g_pix[pb + n0 + tid];
    }
    // Q tile hi/lo: 64 rows x 32 dims
#pragma unroll
    for (int r = 0; r < 2; r++) {
        int idx = tid + r * 256;
        int row = idx >> 3, c4 = idx & 7;
        *(float4*)&Qsh[row * 36 + c4 * 4] = *(const float4*)&g_Qh[(size_t)(pb + n0 + row) * 32 + c4 * 4];
        *(float4*)&Qsl[row * 36 + c4 * 4] = *(const float4*)&g_Ql[(size_t)(pb + n0 + row) * 32 + c4 * 4];
    }

    int mt = w & 3, ntk = w >> 2;          // S: rows mt*16, keys ntk*16
    int wm = w & 3, wslab = (w >> 2) * 128; // PV: rows wm*16, 128-ch slab

    float acc[16][4];
#pragma unroll
    for (int nt = 0; nt < 16; nt++)
#pragma unroll
        for (int r = 0; r < 4; r++) acc[nt][r] = 0.f;

    int nmt = N >> 5;
    for (int it = 0; it < nmt; it++) {
        int mb = pb + it * 32;
        __syncthreads();
        {   // K tile hi/lo
            int row = tid >> 3, c4 = tid & 7;
            *(float4*)&Ksh[row * 36 + c4 * 4] = *(const float4*)&g_Kh[(size_t)(mb + row) * 32 + c4 * 4];
            *(float4*)&Ksl[row * 36 + c4 * 4] = *(const float4*)&g_Kl[(size_t)(mb + row) * 32 + c4 * 4];
        }
#pragma unroll
        for (int r = 0; r < 8; r++) {      // V tile 32 x 256 (stride 264)
            int idx = tid + r * 256;
            int m = idx >> 6, c4 = idx & 63;
            *(float4*)&Vs[m * 264 + c4 * 4] = *(const float4*)&g_V[(size_t)(mb + m) * 264 / 264 * 0 + (size_t)(mb + m) * 256 + c4 * 4];
        }
        __syncthreads();
        {   // S: split-tf32, warp does 16 rows x 16 keys
            float sacc[2][4] = {{0.f,0.f,0.f,0.f},{0.f,0.f,0.f,0.f}};
#pragma unroll
            for (int kt = 0; kt < 4; kt++) {
                int ar = (mt * 16 + g) * 36 + kt * 8 + t;
                int ar8 = ar + 8 * 36;
                u32 ah0 = __float_as_uint(Qsh[ar]);
                u32 ah1 = __float_as_uint(Qsh[ar8]);
                u32 ah2 = __float_as_uint(Qsh[ar + 4]);
                u32 ah3 = __float_as_uint(Qsh[ar8 + 4]);
                u32 al0 = __float_as_uint(Qsl[ar]);
                u32 al1 = __float_as_uint(Qsl[ar8]);
                u32 al2 = __float_as_uint(Qsl[ar + 4]);
                u32 al3 = __float_as_uint(Qsl[ar8 + 4]);
#pragma unroll
                for (int sub = 0; sub < 2; sub++) {
                    int kr = (ntk * 16 + sub * 8 + g) * 36 + kt * 8 + t;
                    u32 bh0 = __float_as_uint(Ksh[kr]);
                    u32 bh1 = __float_as_uint(Ksh[kr + 4]);
                    u32 bl0 = __float_as_uint(Ksl[kr]);
                    u32 bl1 = __float_as_uint(Ksl[kr + 4]);
                    MMA_TF32(sacc[sub], ah0, ah1, ah2, ah3, bh0, bh1);
                    MMA_TF32(sacc[sub], ah0, ah1, ah2, ah3, bl0, bl1);
                    MMA_TF32(sacc[sub], al0, al1, al2, al3, bh0, bh1);
                }
            }
#pragma unroll
            for (int sub = 0; sub < 2; sub++) {
                int pc = ntk * 16 + sub * 8 + 2 * t;
                int pr0 = (mt * 16 + g) * 33 + pc;
                int pr8 = pr0 + 8 * 33;
                Ps[pr0]     = sacc[sub][0];
                Ps[pr0 + 1] = sacc[sub][1];
                Ps[pr8]     = sacc[sub][2];
                Ps[pr8 + 1] = sacc[sub][3];
            }
        }
        __syncthreads();
        {   // online softmax: 4 threads/row, 8 elems each
            int r = tid >> 2, qt = tid & 3;
            float* prow = &Ps[r * 33 + qt * 8];
            float p[8];
#pragma unroll
            for (int j = 0; j < 8; j++) p[j] = prow[j];
            float mx0 = rmax[r];
            float ml = p[0];
#pragma unroll
            for (int j = 1; j < 8; j++) ml = fmaxf(ml, p[j]);
            ml = fmaxf(ml, __shfl_xor_sync(0xffffffffu, ml, 1));
            ml = fmaxf(ml, __shfl_xor_sync(0xffffffffu, ml, 2));
            float nm = fmaxf(mx0, ml);
            float s = 0.f;
#pragma unroll
            for (int j = 0; j < 8; j++) {
                p[j] = __expf(p[j] - nm);
                s += p[j];
                prow[j] = tf32r(p[j]);
            }
            s += __shfl_xor_sync(0xffffffffu, s, 1);
            s += __shfl_xor_sync(0xffffffffu, s, 2);
            if (qt == 0) {
                float sc = __expf(mx0 - nm);
                rsum[r] = rsum[r] * sc + s;
                rmax[r] = nm;
                rscale[r] = sc;
            }
        }
        __syncthreads();
        {   // rescale + PV tf32 MMA (warp: 16 rows x 128 ch)
            float sc0 = rscale[wm * 16 + g];
            float sc1 = rscale[wm * 16 + g + 8];
#pragma unroll
            for (int nt = 0; nt < 16; nt++) {
                acc[nt][0] *= sc0; acc[nt][1] *= sc0;
                acc[nt][2] *= sc1; acc[nt][3] *= sc1;
            }
#pragma unroll
            for (int kt = 0; kt < 4; kt++) {
                int pr0 = (wm * 16 + g) * 33 + kt * 8 + t;
                int pr8 = pr0 + 8 * 33;
                u32 pa0 = __float_as_uint(Ps[pr0]);
                u32 pa1 = __float_as_uint(Ps[pr8]);
                u32 pa2 = __float_as_uint(Ps[pr0 + 4]);
                u32 pa3 = __float_as_uint(Ps[pr8 + 4]);
                int v0r = (kt * 8 + t) * 264 + wslab;
                int v1r = (kt * 8 + t + 4) * 264 + wslab;
#pragma unroll
                for (int nt = 0; nt < 16; nt++) {
                    u32 b0 = __float_as_uint(Vs[v0r + nt * 8 + g]);
                    u32 b1 = __float_as_uint(Vs[v1r + nt * 8 + g]);
                    MMA_TF32(acc[nt], pa0, pa1, pa2, pa3, b0, b1);
                }
            }
        }
    }
    // epilogue: two passes of 32 rows staged via Vs, then coalesced RMW
    float gm = 0.5f * gamma[0];
#pragma unroll
    for (int pass = 0; pass < 2; pass++) {
        __syncthreads();
        if ((wm >> 1) == pass) {
            float f0 = gm / rsum[wm * 16 + g];
            float f1 = gm / rsum[wm * 16 + g + 8];
            int row0 = (wm * 16 + g) - pass * 32;
            int r0 = row0 * 264 + wslab + 2 * t;
            int r8 = (row0 + 8) * 264 + wslab + 2 * t;
#pragma unroll
            for (int nt = 0; nt < 16; nt++) {
                Vs[r0 + nt * 8]     = acc[nt][0] * f0;
                Vs[r0 + nt * 8 + 1] = acc[nt][1] * f0;
                Vs[r8 + nt * 8]     = acc[nt][2] * f1;
                Vs[r8 + nt * 8 + 1] = acc[nt][3] * f1;
            }
        }
        __syncthreads();
        int tn = tid & 7, tc = tid >> 3;
#pragma unroll
        for (int i = 0; i < 4; i++) {
            int row = tn + 8 * i;
            int pa = pas[pass * 32 + row];
#pragma unroll
            for (int j = 0; j < 8; j++) {
                int c = tc * 8 + j;
                out[pa + c * HW] += Vs[row * 264 + c];
            }
        }
    }
}

// ---------------------------------------------------------------- launcher
extern "C" void kernel_launch(void* const* d_in, const int* in_sizes, int n_in,
                              void* d_out, int out_size) {
    const float* x   = (const float*)d_in[0];
    const float* Wq  = (const float*)d_in[1];
    const float* bq  = (const float*)d_in[2];
    const float* q_s = (const float*)d_in[3];
    const float* q_o = (const float*)d_in[4];
    const float* q_m = (const float*)d_in[5];
    const float* q_v = (const float*)d_in[6];
    const float* Wk  = (const float*)d_in[7];
    const float* bk  = (const float*)d_in[8];
    const float* k_s = (const float*)d_in[9];
    const float* k_o = (const float*)d_in[10];
    const float* k_m = (const float*)d_in[11];
    const float* k_v = (const float*)d_in[12];
    const float* Wv  = (const float*)d_in[13];
    const float* bv  = (const float*)d_in[14];
    const float* gam = (const float*)d_in[15];
    float* out = (float*)d_out;

    // dynamic smem for attn: Qsh+Qsl + Ksh+Ksl + Vs + Ps + stats + pas
    const int ASMEM = (64*36*2 + 32*36*2 + 32*264 + 64*33 + 64*3) * 4 + 64 * 4;
    cudaFuncSetAttribute(attn, cudaFuncAttributeMaxDynamicSharedMemorySize, ASMEM);

    prep_wall<<<448, 256>>>(Wq, Wk, Wv);
    prep_bn<<<1, 32>>>(bq, q_s, q_o, q_m, q_v, bk, k_s, k_o, k_m, k_v);
    prep_pix<<<dim3(6, 232), 256>>>();
    copy_x<<<4096, 256>>>((const float4*)x, (float4*)out);
    qkv_gemm<<<dim3(7, 24, 232), 256>>>(x, bv);
    combine_qk<<<dim3(192, 232), 256>>>();
    // win regions (0..11): disjoint pixels within launch -> plain RMW
    attn<<<dim3(16, 96), 256, ASMEM>>>(gam, out, 0);
    // shift regions (12..28): partition of image -> plain RMW
    attn<<<dim3(24, 136), 256, ASMEM>>>(gam, out, 96);
}

// round 8
// speedup vs baseline: 2.5288x; 1.6755x over previous
#include <cuda_runtime.h>
#include <cuda_fp16.h>
#include <math.h>
#include <stdint.h>

// Problem constants (B=8, C=256, H=W=128, win_n=4, shift=16)
#define HW   16384
#define IMG  128
#define NREG 29
#define TOTPIX 229376
#define COUT 448        // 256 V + 96 Pq(3 taps x 32) + 96 Pk

typedef uint32_t u32;

__device__ __forceinline__ float f16r(float v) {
    return __half2float(__float2half_rn(v));
}
__device__ __forceinline__ u32 pack2(float e0, float e1) {   // e0 -> lo half
    __half2 h = __floats2half2_rn(e0, e1);
    return *reinterpret_cast<u32*>(&h);
}

// m16n8k16 fp16 MMA, fp32 accumulate
#define MMA_F16(d, a0, a1, a2, a3, b0, b1)                                           \
    asm volatile("mma.sync.aligned.m16n8k16.row.col.f32.f16.f16.f32 "                \
                 "{%0,%1,%2,%3},{%4,%5,%6,%7},{%8,%9},{%0,%1,%2,%3};"                \
                 : "+f"(d[0]), "+f"(d[1]), "+f"(d[2]), "+f"(d[3])                    \
                 : "r"(a0), "r"(a1), "r"(a2), "r"(a3), "r"(b0), "r"(b1))

// Region tables: 12 win (rows 1..3 x cols 0..3), 9 shift-inner, 8 borders
__constant__ int c_h0[NREG] = {32,32,32,32, 64,64,64,64, 96,96,96,96,
                               16,16,16, 48,48,48, 80,80,80,
                               0,0,0, 16,16, 112,112,112};
__constant__ int c_w0[NREG] = {0,32,64,96, 0,32,64,96, 0,32,64,96,
                               16,48,80, 16,48,80, 16,48,80,
                               0,16,112, 0,112, 0,16,112};
__constant__ int c_Hr[NREG] = {32,32,32,32,32,32,32,32,32,32,32,32,
                               32,32,32,32,32,32,32,32,32,
                               16,16,16, 96,96, 16,16,16};
__constant__ int c_Wr[NREG] = {32,32,32,32,32,32,32,32,32,32,32,32,
                               32,32,32,32,32,32,32,32,32,
                               16,96,16, 16,16, 16,96,16};
__constant__ int c_N[NREG]  = {1024,1024,1024,1024,1024,1024,1024,1024,1024,1024,1024,1024,
                               1024,1024,1024,1024,1024,1024,1024,1024,1024,
                               256,1536,256, 1536,1536, 256,1536,256};
__constant__ int c_base[NREG] = {0,8192,16384,24576,32768,40960,49152,57344,65536,73728,81920,90112,
                                 98304,106496,114688,122880,131072,139264,147456,155648,163840,
                                 172032,174080,186368, 188416,200704, 212992,215040,227328};

// Scratch (__device__ globals)
static __device__ u32   g_W16h[COUT * 128];                  // [co][ci-pair] fp16x2 hi
static __device__ u32   g_W16l[COUT * 128];                  // lo residual
static __device__ u32   g_V16a[(size_t)TOTPIX * 128];        // [pix][ch-pair] fp16x2
static __device__ u32   g_V16 [(size_t)TOTPIX * 128];        // [tile][ch][key-pair]
static __device__ float g_PQK[(size_t)TOTPIX * 192];
static __device__ u32   g_Q16h[(size_t)TOTPIX * 16];         // [pix][d-pair]
static __device__ u32   g_Q16l[(size_t)TOTPIX * 16];
static __device__ u32   g_K16h[(size_t)TOTPIX * 16];
static __device__ u32   g_K16l[(size_t)TOTPIX * 16];
static __device__ int   g_pix[TOTPIX];
static __device__ float g_qsc[32], g_qof[32], g_ksc[32], g_kof[32];

// ---------------------------------------------------------------- prep kernels
__device__ __forceinline__ float wall_val(const float* Wq, const float* Wk,
                                          const float* Wv, int co, int ci) {
    if (co < 256) return Wv[co * 256 + ci];
    if (co < 352) { int t = (co - 256) >> 5, c8 = (co - 256) & 31;
                    return Wq[(c8 * 256 + ci) * 3 + t]; }
    { int t = (co - 352) >> 5, c8 = (co - 352) & 31;
      return Wk[(c8 * 256 + ci) * 3 + t]; }
}

__global__ void prep_wall(const float* __restrict__ Wq, const float* __restrict__ Wk,
                          const float* __restrict__ Wv) {
    int idx = blockIdx.x * 256 + threadIdx.x;
    if (idx >= COUT * 128) return;
    int co = idx >> 7, cp = idx & 127;
    float v0 = wall_val(Wq, Wk, Wv, co, 2 * cp);
    float v1 = wall_val(Wq, Wk, Wv, co, 2 * cp + 1);
    g_W16h[idx] = pack2(v0, v1);
    g_W16l[idx] = pack2(v0 - f16r(v0), v1 - f16r(v1));
}

__global__ void prep_bn(const float* bq, const float* qs, const float* qo, const float* qm, const float* qv,
                        const float* bk, const float* ks, const float* ko, const float* km, const float* kv) {
    int c = threadIdx.x;
    if (c >= 32) return;
    float sc = qs[c] * rsqrtf(qv[c] + 1e-5f);
    g_qsc[c] = sc;
    g_qof[c] = bq[c] * sc + qo[c] - qm[c] * sc;
    sc = ks[c] * rsqrtf(kv[c] + 1e-5f);
    g_ksc[c] = sc;
    g_kof[c] = bk[c] * sc + ko[c] - km[c] * sc;
}

__global__ void prep_pix() {
    int inst = blockIdx.y;
    int region = inst >> 3, b = inst & 7;
    int N = c_N[region];
    int n = blockIdx.x * 256 + threadIdx.x;
    if (n >= N) return;
    int Wr = c_Wr[region];
    int h = n / Wr, w = n - h * Wr;
    g_pix[c_base[region] + b * N + n] = b * (256 * HW) + (c_h0[region] + h) * IMG + c_w0[region] + w;
}

__global__ void copy_x(const float4* __restrict__ x, float4* __restrict__ o) {
    int i = blockIdx.x * blockDim.x + threadIdx.x;
    int stride = gridDim.x * blockDim.x;
    for (; i < 8388608; i += stride) o[i] = x[i];
}

// ---------------- QKV GEMM: [pix,256]@[256,448], split-fp16 MMA (~fp32 accurate)
__global__ __launch_bounds__(256) void qkv_gemm(const float* __restrict__ x,
                                                const float* __restrict__ bv) {
    int inst = blockIdx.z;
    int region = inst >> 3, b = inst & 7;
    int N = c_N[region];
    int m0 = blockIdx.y * 64;
    if (m0 >= N) return;
    int pb = c_base[region] + b * N;
    int n0 = blockIdx.x * 64;

    __shared__ __align__(16) u32 Ah[64 * 20], Al[64 * 20];
    __shared__ __align__(16) u32 Bh[64 * 20], Bl[64 * 20];
    __shared__ int pas[64];

    int tid = threadIdx.x;
    if (tid < 64) pas[tid] = g_pix[pb + m0 + tid];
    __syncthreads();

    int lane = tid & 31, w = tid >> 5;
    int g = lane >> 2, t = lane & 3;
    int mt = w & 3, ntq = w >> 2;

    float acc[4][4];
#pragma unroll
    for (int i = 0; i < 4; i++)
#pragma unroll
        for (int j = 0; j < 4; j++) acc[i][j] = 0.f;

    for (int k0 = 0; k0 < 256; k0 += 32) {
        __syncthreads();
#pragma unroll
        for (int r = 0; r < 4; r++) {              // A: 64 m x 16 k-pairs
            int idx = tid + r * 256;
            int m = idx & 63, kp = idx >> 6;
            float v0 = x[pas[m] + (k0 + 2 * kp) * HW];
            float v1 = x[pas[m] + (k0 + 2 * kp + 1) * HW];
            Ah[m * 20 + kp] = pack2(v0, v1);
            Al[m * 20 + kp] = pack2(v0 - f16r(v0), v1 - f16r(v1));
        }
        {                                          // B: 64 n x 16 k-pairs
            int n = tid >> 2, c4 = tid & 3;
            *(float4*)&Bh[n * 20 + c4 * 4] = *(const float4*)&g_W16h[(size_t)(n0 + n) * 128 + k0 / 2 + c4 * 4];
            *(float4*)&Bl[n * 20 + c4 * 4] = *(const float4*)&g_W16l[(size_t)(n0 + n) * 128 + k0 / 2 + c4 * 4];
        }
        __syncthreads();
#pragma unroll
        for (int kt = 0; kt < 2; kt++) {
            int ar = (mt * 16 + g) * 20 + kt * 8 + t;
            u32 ah0 = Ah[ar], ah1 = Ah[ar + 160], ah2 = Ah[ar + 4], ah3 = Ah[ar + 164];
            u32 al0 = Al[ar], al1 = Al[ar + 160], al2 = Al[ar + 4], al3 = Al[ar + 164];
#pragma unroll
            for (int ns = 0; ns < 4; ns++) {
                int nr = (ntq * 32 + ns * 8 + g) * 20 + kt * 8 + t;
                u32 bh0 = Bh[nr], bh1 = Bh[nr + 4];
                u32 bl0 = Bl[nr], bl1 = Bl[nr + 4];
                MMA_F16(acc[ns], ah0, ah1, ah2, ah3, bh0, bh1);
                MMA_F16(acc[ns], al0, al1, al2, al3, bh0, bh1);
                MMA_F16(acc[ns], ah0, ah1, ah2, ah3, bl0, bl1);
            }
        }
    }
#pragma unroll
    for (int ns = 0; ns < 4; ns++) {
        int co = n0 + ntq * 32 + ns * 8 + 2 * t;
        size_t mg  = (size_t)(pb + m0 + mt * 16 + g);
        size_t mg8 = mg + 8;
        if (co < 256) {
            float b0 = bv[co], b1 = bv[co + 1];
            g_V16a[mg  * 128 + co / 2] = pack2(acc[ns][0] + b0, acc[ns][1] + b1);
            g_V16a[mg8 * 128 + co / 2] = pack2(acc[ns][2] + b0, acc[ns][3] + b1);
        } else {
            int cp = co - 256;
            g_PQK[mg  * 192 + cp]     = acc[ns][0];
            g_PQK[mg  * 192 + cp + 1] = acc[ns][1];
            g_PQK[mg8 * 192 + cp]     = acc[ns][2];
            g_PQK[mg8 * 192 + cp + 1] = acc[ns][3];
        }
    }
}

// ---------------- V transpose/pack: [pix][ch-pair] -> [tile][ch][key-pair]
__global__ __launch_bounds__(256) void v_pack() {
    __shared__ u32 Vt[32 * 129];
    int tile = blockIdx.x;
    int tid = threadIdx.x;
    size_t base = (size_t)tile * 4096;
#pragma unroll
    for (int r = 0; r < 16; r++) {
        int idx = tid + r * 256;                  // key*128 + cp
        Vt[(idx >> 7) * 129 + (idx & 127)] = g_V16a[base + idx];
    }
    __syncthreads();
#pragma unroll
    for (int r = 0; r < 8; r++) {
        int idx = tid + r * 256;                  // 128 cp x 16 kp
        int cp = idx >> 4, kp = idx & 15;
        u32 a = Vt[(2 * kp) * 129 + cp];
        u32 b = Vt[(2 * kp + 1) * 129 + cp];
        g_V16[base + (size_t)(2 * cp) * 16 + kp]     = __byte_perm(a, b, 0x5410);
        g_V16[base + (size_t)(2 * cp + 1) * 16 + kp] = __byte_perm(a, b, 0x7632);
    }
}

// ------------- combine conv taps + BN + ReLU, split Q/K into fp16 hi/lo pairs
__global__ void combine_qk() {
    int inst = blockIdx.y;
    int region = inst >> 3, b = inst & 7;
    int N = c_N[region];
    int idx = blockIdx.x * 256 + threadIdx.x;
    int n = idx >> 4;
    if (n >= N) return;
    int cp = idx & 15, c0 = 2 * cp;
    int Wr = c_Wr[region], Hr = c_Hr[region];
    int pb = c_base[region] + b * N;
    int h = n / Wr, w = n - h * Wr;
    size_t rowp = (size_t)(pb + n) * 192;

    float2 q = *(float2*)&g_PQK[rowp + 32 + c0];
    if (w > 0)      { float2 a = *(float2*)&g_PQK[rowp - 192 + c0]; q.x += a.x; q.y += a.y; }
    if (w < Wr - 1) { float2 a = *(float2*)&g_PQK[rowp + 192 + 64 + c0]; q.x += a.x; q.y += a.y; }
    q.x = fmaxf(fmaf(q.x, g_qsc[c0], g_qof[c0]), 0.f);
    q.y = fmaxf(fmaf(q.y, g_qsc[c0 + 1], g_qof[c0 + 1]), 0.f);
    g_Q16h[(size_t)(pb + n) * 16 + cp] = pack2(q.x, q.y);
    g_Q16l[(size_t)(pb + n) * 16 + cp] = pack2(q.x - f16r(q.x), q.y - f16r(q.y));

    float2 k = *(float2*)&g_PQK[rowp + 96 + 32 + c0];
    if (h > 0)      { float2 a = *(float2*)&g_PQK[rowp - (size_t)Wr * 192 + 96 + c0]; k.x += a.x; k.y += a.y; }
    if (h < Hr - 1) { float2 a = *(float2*)&g_PQK[rowp + (size_t)Wr * 192 + 96 + 64 + c0]; k.x += a.x; k.y += a.y; }
    k.x = fmaxf(fmaf(k.x, g_ksc[c0], g_kof[c0]), 0.f);
    k.y = fmaxf(fmaf(k.y, g_ksc[c0 + 1], g_kof[c0 + 1]), 0.f);
    g_K16h[(size_t)(pb + n) * 16 + cp] = pack2(k.x, k.y);
    g_K16l[(size_t)(pb + n) * 16 + cp] = pack2(k.x - f16r(k.x), k.y - f16r(k.y));
}

// ------------------- fp16 tensor-core flash attention, 64 q-rows/CTA
// S = split-fp16 (3 MMA, ~fp32); PV = plain fp16. Two launches (win/shift).
// smem offsets in u32 units:
#define OQH 0
#define OQL 1280
#define OKH 2560
#define OKL 3200
#define OVS 3840
#define OPS 8960
#define OP16 11072
#define OSTAT 12352
#define ASMEM ((12352 + 256) * 4)

__global__ __launch_bounds__(256, 2) void attn(const float* __restrict__ gamma,
                                               float* __restrict__ out, int inst0) {
    extern __shared__ u32 sm32[];
    u32* Qh = sm32 + OQH;          // 64 x 20 (16 used)
    u32* Ql = sm32 + OQL;
    u32* Kh = sm32 + OKH;          // 32 x 20
    u32* Kl = sm32 + OKL;
    u32* Vs = sm32 + OVS;          // 256 x 20
    float* Ps  = (float*)(sm32 + OPS);    // 64 x 33
    u32* Ps16 = sm32 + OP16;       // 64 x 20 (16 used)
    float* rmax = (float*)(sm32 + OSTAT);
    float* rsum = rmax + 64;
    float* rscale = rsum + 64;
    int* pas = (int*)(rscale + 64);
    float* stage = (float*)Vs;     // epilogue union: 32 x 264 fp32 (fits Vs+Ps+Ps16)

    int inst = inst0 + blockIdx.y;
    int region = inst >> 3, b = inst & 7;
    int N = c_N[region];
    int n0 = blockIdx.x * 64;
    if (n0 >= N) return;
    int pb = c_base[region] + b * N;

    int tid = threadIdx.x;
    int lane = tid & 31, w = tid >> 5;
    int g = lane >> 2, t = lane & 3;
    if (tid < 64) {
        rmax[tid] = -1e30f; rsum[tid] = 0.f;
        pas[tid] = g_pix[pb + n0 + tid];
    }
    {   // Q tile hi/lo: 64 rows x 4 float4 each (exactly 256 threads)
        int row = tid >> 2, c4 = tid & 3;
        *(float4*)&Qh[row * 20 + c4 * 4] = *(const float4*)&g_Q16h[(size_t)(pb + n0 + row) * 16 + c4 * 4];
        *(float4*)&Ql[row * 20 + c4 * 4] = *(const float4*)&g_Q16l[(size_t)(pb + n0 + row) * 16 + c4 * 4];
    }

    int mt = w & 3, ntk = w >> 2;             // S mapping
    int wm = w & 3, wslab = (w >> 2) * 128;   // PV mapping

    float acc[16][4];
#pragma unroll
    for (int nt = 0; nt < 16; nt++)
#pragma unroll
        for (int r = 0; r < 4; r++) acc[nt][r] = 0.f;

    int nmt = N >> 5;
    for (int it = 0; it < nmt; it++) {
        int mb = pb + it * 32;
        size_t vbase = (size_t)(mb >> 5) * 4096;
        __syncthreads();
        {   // K tile hi/lo: 32 rows x 4 float4 x 2 buffers
            int row = (tid & 127) >> 2, c4 = tid & 3;
            const u32* src = (tid < 128) ? g_K16h : g_K16l;
            u32* dst = (tid < 128) ? Kh : Kl;
            *(float4*)&dst[row * 20 + c4 * 4] = *(const float4*)&src[(size_t)(mb + row) * 16 + c4 * 4];
        }
#pragma unroll
        for (int r = 0; r < 4; r++) {   // V tile: 256 ch x 4 float4
            int idx = tid + r * 256;
            int ch = idx >> 2, c4 = idx & 3;
            *(float4*)&Vs[ch * 20 + c4 * 4] = *(const float4*)&g_V16[vbase + ch * 16 + c4 * 4];
        }
        __syncthreads();
        {   // S: split-fp16, warp does 16 rows x 16 keys
            float sacc[2][4] = {{0.f,0.f,0.f,0.f},{0.f,0.f,0.f,0.f}};
#pragma unroll
            for (int kt = 0; kt < 2; kt++) {
                int ar = (mt * 16 + g) * 20 + kt * 8 + t;
                u32 ah0 = Qh[ar], ah1 = Qh[ar + 160], ah2 = Qh[ar + 4], ah3 = Qh[ar + 164];
                u32 al0 = Ql[ar], al1 = Ql[ar + 160], al2 = Ql[ar + 4], al3 = Ql[ar + 164];
#pragma unroll
                for (int sub = 0; sub < 2; sub++) {
                    int kr = (ntk * 16 + sub * 8 + g) * 20 + kt * 8 + t;
                    u32 bh0 = Kh[kr], bh1 = Kh[kr + 4];
                    u32 bl0 = Kl[kr], bl1 = Kl[kr + 4];
                    MMA_F16(sacc[sub], ah0, ah1, ah2, ah3, bh0, bh1);
                    MMA_F16(sacc[sub], al0, al1, al2, al3, bh0, bh1);
                    MMA_F16(sacc[sub], ah0, ah1, ah2, ah3, bl0, bl1);
                }
            }
#pragma unroll
            for (int sub = 0; sub < 2; sub++) {
                int pc = ntk * 16 + sub * 8 + 2 * t;
                int pr0 = (mt * 16 + g) * 33 + pc;
                int pr8 = pr0 + 8 * 33;
                Ps[pr0]     = sacc[sub][0];
                Ps[pr0 + 1] = sacc[sub][1];
                Ps[pr8]     = sacc[sub][2];
                Ps[pr8 + 1] = sacc[sub][3];
            }
        }
        __syncthreads();
        {   // online softmax: 4 threads/row, 8 keys each; write fp16 pairs
            int r = tid >> 2, qt = tid & 3;
            float* prow = &Ps[r * 33 + qt * 8];
            float p[8];
#pragma unroll
            for (int j = 0; j < 8; j++) p[j] = prow[j];
            float mx0 = rmax[r];
            float ml = p[0];
#pragma unroll
            for (int j = 1; j < 8; j++) ml = fmaxf(ml, p[j]);
            ml = fmaxf(ml, __shfl_xor_sync(0xffffffffu, ml, 1));
            ml = fmaxf(ml, __shfl_xor_sync(0xffffffffu, ml, 2));
            float nm = fmaxf(mx0, ml);
            float s = 0.f;
#pragma unroll
            for (int j = 0; j < 8; j++) {
                p[j] = __expf(p[j] - nm);
                s += p[j];
            }
            u32* p16 = &Ps16[r * 20 + qt * 4];
            p16[0] = pack2(p[0], p[1]);
            p16[1] = pack2(p[2], p[3]);
            p16[2] = pack2(p[4], p[5]);
            p16[3] = pack2(p[6], p[7]);
            s += __shfl_xor_sync(0xffffffffu, s, 1);
            s += __shfl_xor_sync(0xffffffffu, s, 2);
            if (qt == 0) {
                float sc = __expf(mx0 - nm);
                rsum[r] = rsum[r] * sc + s;
                rmax[r] = nm;
                rscale[r] = sc;
            }
        }
        __syncthreads();
        {   // rescale + PV fp16 MMA (warp: 16 rows x 128 ch)
            float sc0 = rscale[wm * 16 + g];
            float sc1 = rscale[wm * 16 + g + 8];
#pragma unroll
            for (int nt = 0; nt < 16; nt++) {
                acc[nt][0] *= sc0; acc[nt][1] *= sc0;
                acc[nt][2] *= sc1; acc[nt][3] *= sc1;
            }
#pragma unroll
            for (int kt = 0; kt < 2; kt++) {
                int pr = (wm * 16 + g) * 20 + kt * 8 + t;
                u32 pa0 = Ps16[pr], pa1 = Ps16[pr + 160], pa2 = Ps16[pr + 4], pa3 = Ps16[pr + 164];
#pragma unroll
                for (int nt = 0; nt < 16; nt++) {
                    int vr = (wslab + nt * 8 + g) * 20 + kt * 8 + t;
                    MMA_F16(acc[nt], pa0, pa1, pa2, pa3, Vs[vr], Vs[vr + 4]);
                }
            }
        }
    }
    // epilogue: two passes of 32 rows staged via `stage`, then coalesced RMW
    float gm = 0.5f * gamma[0];
#pragma unroll
    for (int pass = 0; pass < 2; pass++) {
        __syncthreads();
        if ((wm >> 1) == pass) {
            float f0 = gm / rsum[wm * 16 + g];
            float f1 = gm / rsum[wm * 16 + g + 8];
            int row0 = (wm * 16 + g) - pass * 32;
            int r0 = row0 * 264 + wslab + 2 * t;
            int r8 = (row0 + 8) * 264 + wslab + 2 * t;
#pragma unroll
            for (int nt = 0; nt < 16; nt++) {
                stage[r0 + nt * 8]     = acc[nt][0] * f0;
                stage[r0 + nt * 8 + 1] = acc[nt][1] * f0;
                stage[r8 + nt * 8]     = acc[nt][2] * f1;
                stage[r8 + nt * 8 + 1] = acc[nt][3] * f1;
            }
        }
        __syncthreads();
        int tn = tid & 7, tc = tid >> 3;
#pragma unroll
        for (int i = 0; i < 4; i++) {
            int row = tn + 8 * i;
            int pa = pas[pass * 32 + row];
#pragma unroll
            for (int j = 0; j < 8; j++) {
                int c = tc * 8 + j;
                out[pa + c * HW] += stage[row * 264 + c];
            }
        }
    }
}

// ---------------------------------------------------------------- launcher
extern "C" void kernel_launch(void* const* d_in, const int* in_sizes, int n_in,
                              void* d_out, int out_size) {
    const float* x   = (const float*)d_in[0];
    const float* Wq  = (const float*)d_in[1];
    const float* bq  = (const float*)d_in[2];
    const float* q_s = (const float*)d_in[3];
    const float* q_o = (const float*)d_in[4];
    const float* q_m = (const float*)d_in[5];
    const float* q_v = (const float*)d_in[6];
    const float* Wk  = (const float*)d_in[7];
    const float* bk  = (const float*)d_in[8];
    const float* k_s = (const float*)d_in[9];
    const float* k_o = (const float*)d_in[10];
    const float* k_m = (const float*)d_in[11];
    const float* k_v = (const float*)d_in[12];
    const float* Wv  = (const float*)d_in[13];
    const float* bv  = (const float*)d_in[14];
    const float* gam = (const float*)d_in[15];
    float* out = (float*)d_out;

    cudaFuncSetAttribute(attn, cudaFuncAttributeMaxDynamicSharedMemorySize, ASMEM);

    prep_wall<<<224, 256>>>(Wq, Wk, Wv);
    prep_bn<<<1, 32>>>(bq, q_s, q_o, q_m, q_v, bk, k_s, k_o, k_m, k_v);
    prep_pix<<<dim3(6, 232), 256>>>();
    copy_x<<<4096, 256>>>((const float4*)x, (float4*)out);
    qkv_gemm<<<dim3(7, 24, 232), 256>>>(x, bv);
    v_pack<<<TOTPIX / 32, 256>>>();
    combine_qk<<<dim3(96, 232), 256>>>();
    // win regions (0..11): disjoint pixels within launch -> plain RMW
    attn<<<dim3(16, 96), 256, ASMEM>>>(gam, out, 0);
    // shift regions (12..28): partition of image -> plain RMW
    attn<<<dim3(24, 136), 256, ASMEM>>>(gam, out, 96);
}

// round 9
// speedup vs baseline: 2.7498x; 1.0874x over previous
#include <cuda_runtime.h>
#include <cuda_fp16.h>
#include <math.h>
#include <stdint.h>

// Problem constants (B=8, C=256, H=W=128, win_n=4, shift=16)
#define HW   16384
#define IMG  128
#define NREG 29
#define TOTPIX 229376
#define COUT 448        // 256 V + 96 Pq(3 taps x 32) + 96 Pk

typedef uint32_t u32;

__device__ __forceinline__ float f16r(float v) {
    return __half2float(__float2half_rn(v));
}
__device__ __forceinline__ u32 pack2(float e0, float e1) {   // e0 -> lo half
    __half2 h = __floats2half2_rn(e0, e1);
    return *reinterpret_cast<u32*>(&h);
}

// m16n8k16 fp16 MMA, fp32 accumulate
#define MMA_F16(d, a0, a1, a2, a3, b0, b1)                                           \
    asm volatile("mma.sync.aligned.m16n8k16.row.col.f32.f16.f16.f32 "                \
                 "{%0,%1,%2,%3},{%4,%5,%6,%7},{%8,%9},{%0,%1,%2,%3};"                \
                 : "+f"(d[0]), "+f"(d[1]), "+f"(d[2]), "+f"(d[3])                    \
                 : "r"(a0), "r"(a1), "r"(a2), "r"(a3), "r"(b0), "r"(b1))

__device__ __forceinline__ void cpa16(u32 dst, const u32* src) {
    asm volatile("cp.async.cg.shared.global [%0], [%1], 16;" :: "r"(dst), "l"(src));
}
#define CPA_COMMIT asm volatile("cp.async.commit_group;")
#define CPA_WAIT1  asm volatile("cp.async.wait_group 1;")
#define CPA_WAIT0  asm volatile("cp.async.wait_all;")

// Region tables: 12 win (rows 1..3 x cols 0..3), 9 shift-inner, 8 borders
__constant__ int c_h0[NREG] = {32,32,32,32, 64,64,64,64, 96,96,96,96,
                               16,16,16, 48,48,48, 80,80,80,
                               0,0,0, 16,16, 112,112,112};
__constant__ int c_w0[NREG] = {0,32,64,96, 0,32,64,96, 0,32,64,96,
                               16,48,80, 16,48,80, 16,48,80,
                               0,16,112, 0,112, 0,16,112};
__constant__ int c_Hr[NREG] = {32,32,32,32,32,32,32,32,32,32,32,32,
                               32,32,32,32,32,32,32,32,32,
                               16,16,16, 96,96, 16,16,16};
__constant__ int c_Wr[NREG] = {32,32,32,32,32,32,32,32,32,32,32,32,
                               32,32,32,32,32,32,32,32,32,
                               16,96,16, 16,16, 16,96,16};
__constant__ int c_N[NREG]  = {1024,1024,1024,1024,1024,1024,1024,1024,1024,1024,1024,1024,
                               1024,1024,1024,1024,1024,1024,1024,1024,1024,
                               256,1536,256, 1536,1536, 256,1536,256};
__constant__ int c_base[NREG] = {0,8192,16384,24576,32768,40960,49152,57344,65536,73728,81920,90112,
                                 98304,106496,114688,122880,131072,139264,147456,155648,163840,
                                 172032,174080,186368, 188416,200704, 212992,215040,227328};

// Scratch (__device__ globals)
static __device__ u32   g_W16h[COUT * 128];                  // [co][ci-pair] fp16x2 hi
static __device__ u32   g_W16l[COUT * 128];                  // lo residual
static __device__ u32   g_V16a[(size_t)TOTPIX * 128];        // [pix][ch-pair] fp16x2
static __device__ u32   g_V16 [(size_t)TOTPIX * 128];        // [tile][ch][key-pair]
static __device__ float g_PQK[(size_t)TOTPIX * 192];
static __device__ u32   g_Q16h[(size_t)TOTPIX * 16];         // [pix][d-pair]
static __device__ u32   g_Q16l[(size_t)TOTPIX * 16];
static __device__ u32   g_K16h[(size_t)TOTPIX * 16];
static __device__ u32   g_K16l[(size_t)TOTPIX * 16];
static __device__ int   g_pix[TOTPIX];
static __device__ float g_qsc[32], g_qof[32], g_ksc[32], g_kof[32];

// ---------------------------------------------------------------- prep kernels
__device__ __forceinline__ float wall_val(const float* Wq, const float* Wk,
                                          const float* Wv, int co, int ci) {
    if (co < 256) return Wv[co * 256 + ci];
    if (co < 352) { int t = (co - 256) >> 5, c8 = (co - 256) & 31;
                    return Wq[(c8 * 256 + ci) * 3 + t]; }
    { int t = (co - 352) >> 5, c8 = (co - 352) & 31;
      return Wk[(c8 * 256 + ci) * 3 + t]; }
}

__global__ void prep_wall(const float* __restrict__ Wq, const float* __restrict__ Wk,
                          const float* __restrict__ Wv) {
    int idx = blockIdx.x * 256 + threadIdx.x;
    if (idx >= COUT * 128) return;
    int co = idx >> 7, cp = idx & 127;
    float v0 = wall_val(Wq, Wk, Wv, co, 2 * cp);
    float v1 = wall_val(Wq, Wk, Wv, co, 2 * cp + 1);
    g_W16h[idx] = pack2(v0, v1);
    g_W16l[idx] = pack2(v0 - f16r(v0), v1 - f16r(v1));
}

__global__ void prep_bn(const float* bq, const float* qs, const float* qo, const float* qm, const float* qv,
                        const float* bk, const float* ks, const float* ko, const float* km, const float* kv) {
    int c = threadIdx.x;
    if (c >= 32) return;
    float sc = qs[c] * rsqrtf(qv[c] + 1e-5f);
    g_qsc[c] = sc;
    g_qof[c] = bq[c] * sc + qo[c] - qm[c] * sc;
    sc = ks[c] * rsqrtf(kv[c] + 1e-5f);
    g_ksc[c] = sc;
    g_kof[c] = bk[c] * sc + ko[c] - km[c] * sc;
}

__global__ void prep_pix() {
    int inst = blockIdx.y;
    int region = inst >> 3, b = inst & 7;
    int N = c_N[region];
    int n = blockIdx.x * 256 + threadIdx.x;
    if (n >= N) return;
    int Wr = c_Wr[region];
    int h = n / Wr, w = n - h * Wr;
    g_pix[c_base[region] + b * N + n] = b * (256 * HW) + (c_h0[region] + h) * IMG + c_w0[region] + w;
}

__global__ void copy_x(const float4* __restrict__ x, float4* __restrict__ o) {
    int i = blockIdx.x * blockDim.x + threadIdx.x;
    int stride = gridDim.x * blockDim.x;
    for (; i < 8388608; i += stride) o[i] = x[i];
}

// ---------------- QKV GEMM: [pix,256]@[256,448]
// V-column tiles (n0 < 256): plain fp16 (1 MMA).  Q/K tap tiles: split-fp16 x3.
__global__ __launch_bounds__(256) void qkv_gemm(const float* __restrict__ x,
                                                const float* __restrict__ bv) {
    int inst = blockIdx.z;
    int region = inst >> 3, b = inst & 7;
    int N = c_N[region];
    int m0 = blockIdx.y * 64;
    if (m0 >= N) return;
    int pb = c_base[region] + b * N;
    int n0 = blockIdx.x * 64;
    bool vt = (n0 < 256);          // pure-V tile: plain fp16

    __shared__ __align__(16) u32 Ah[64 * 20], Al[64 * 20];
    __shared__ __align__(16) u32 Bh[64 * 20], Bl[64 * 20];
    __shared__ int pas[64];

    int tid = threadIdx.x;
    if (tid < 64) pas[tid] = g_pix[pb + m0 + tid];
    __syncthreads();

    int lane = tid & 31, w = tid >> 5;
    int g = lane >> 2, t = lane & 3;
    int mt = w & 3, ntq = w >> 2;

    float acc[4][4];
#pragma unroll
    for (int i = 0; i < 4; i++)
#pragma unroll
        for (int j = 0; j < 4; j++) acc[i][j] = 0.f;

    for (int k0 = 0; k0 < 256; k0 += 32) {
        __syncthreads();
#pragma unroll
        for (int r = 0; r < 4; r++) {              // A: 64 m x 16 k-pairs
            int idx = tid + r * 256;
            int m = idx & 63, kp = idx >> 6;
            float v0 = x[pas[m] + (k0 + 2 * kp) * HW];
            float v1 = x[pas[m] + (k0 + 2 * kp + 1) * HW];
            Ah[m * 20 + kp] = pack2(v0, v1);
            if (!vt) Al[m * 20 + kp] = pack2(v0 - f16r(v0), v1 - f16r(v1));
        }
        {                                          // B: 64 n x 16 k-pairs
            int n = tid >> 2, c4 = tid & 3;
            *(float4*)&Bh[n * 20 + c4 * 4] = *(const float4*)&g_W16h[(size_t)(n0 + n) * 128 + k0 / 2 + c4 * 4];
            if (!vt)
                *(float4*)&Bl[n * 20 + c4 * 4] = *(const float4*)&g_W16l[(size_t)(n0 + n) * 128 + k0 / 2 + c4 * 4];
        }
        __syncthreads();
#pragma unroll
        for (int kt = 0; kt < 2; kt++) {
            int ar = (mt * 16 + g) * 20 + kt * 8 + t;
            u32 ah0 = Ah[ar], ah1 = Ah[ar + 160], ah2 = Ah[ar + 4], ah3 = Ah[ar + 164];
#pragma unroll
            for (int ns = 0; ns < 4; ns++) {
                int nr = (ntq * 32 + ns * 8 + g) * 20 + kt * 8 + t;
                u32 bh0 = Bh[nr], bh1 = Bh[nr + 4];
                MMA_F16(acc[ns], ah0, ah1, ah2, ah3, bh0, bh1);
                if (!vt) {
                    u32 al0 = Al[ar], al1 = Al[ar + 160], al2 = Al[ar + 4], al3 = Al[ar + 164];
                    u32 bl0 = Bl[nr], bl1 = Bl[nr + 4];
                    MMA_F16(acc[ns], al0, al1, al2, al3, bh0, bh1);
                    MMA_F16(acc[ns], ah0, ah1, ah2, ah3, bl0, bl1);
                }
            }
        }
    }
#pragma unroll
    for (int ns = 0; ns < 4; ns++) {
        int co = n0 + ntq * 32 + ns * 8 + 2 * t;
        size_t mg  = (size_t)(pb + m0 + mt * 16 + g);
        size_t mg8 = mg + 8;
        if (co < 256) {
            float b0 = bv[co], b1 = bv[co + 1];
            g_V16a[mg  * 128 + co / 2] = pack2(acc[ns][0] + b0, acc[ns][1] + b1);
            g_V16a[mg8 * 128 + co / 2] = pack2(acc[ns][2] + b0, acc[ns][3] + b1);
        } else {
            int cp = co - 256;
            g_PQK[mg  * 192 + cp]     = acc[ns][0];
            g_PQK[mg  * 192 + cp + 1] = acc[ns][1];
            g_PQK[mg8 * 192 + cp]     = acc[ns][2];
            g_PQK[mg8 * 192 + cp + 1] = acc[ns][3];
        }
    }
}

// ---------------- V transpose/pack: [pix][ch-pair] -> [tile][ch][key-pair]
__global__ __launch_bounds__(256) void v_pack() {
    __shared__ u32 Vt[32 * 129];
    int tile = blockIdx.x;
    int tid = threadIdx.x;
    size_t base = (size_t)tile * 4096;
#pragma unroll
    for (int r = 0; r < 16; r++) {
        int idx = tid + r * 256;
        Vt[(idx >> 7) * 129 + (idx & 127)] = g_V16a[base + idx];
    }
    __syncthreads();
#pragma unroll
    for (int r = 0; r < 8; r++) {
        int idx = tid + r * 256;
        int cp = idx >> 4, kp = idx & 15;
        u32 a = Vt[(2 * kp) * 129 + cp];
        u32 b = Vt[(2 * kp + 1) * 129 + cp];
        g_V16[base + (size_t)(2 * cp) * 16 + kp]     = __byte_perm(a, b, 0x5410);
        g_V16[base + (size_t)(2 * cp + 1) * 16 + kp] = __byte_perm(a, b, 0x7632);
    }
}

// ------------- combine conv taps + BN + ReLU, split Q/K into fp16 hi/lo pairs
__global__ void combine_qk() {
    int inst = blockIdx.y;
    int region = inst >> 3, b = inst & 7;
    int N = c_N[region];
    int idx = blockIdx.x * 256 + threadIdx.x;
    int n = idx >> 4;
    if (n >= N) return;
    int cp = idx & 15, c0 = 2 * cp;
    int Wr = c_Wr[region], Hr = c_Hr[region];
    int pb = c_base[region] + b * N;
    int h = n / Wr, w = n - h * Wr;
    size_t rowp = (size_t)(pb + n) * 192;

    float2 q = *(float2*)&g_PQK[rowp + 32 + c0];
    if (w > 0)      { float2 a = *(float2*)&g_PQK[rowp - 192 + c0]; q.x += a.x; q.y += a.y; }
    if (w < Wr - 1) { float2 a = *(float2*)&g_PQK[rowp + 192 + 64 + c0]; q.x += a.x; q.y += a.y; }
    q.x = fmaxf(fmaf(q.x, g_qsc[c0], g_qof[c0]), 0.f);
    q.y = fmaxf(fmaf(q.y, g_qsc[c0 + 1], g_qof[c0 + 1]), 0.f);
    g_Q16h[(size_t)(pb + n) * 16 + cp] = pack2(q.x, q.y);
    g_Q16l[(size_t)(pb + n) * 16 + cp] = pack2(q.x - f16r(q.x), q.y - f16r(q.y));

    float2 k = *(float2*)&g_PQK[rowp + 96 + 32 + c0];
    if (h > 0)      { float2 a = *(float2*)&g_PQK[rowp - (size_t)Wr * 192 + 96 + c0]; k.x += a.x; k.y += a.y; }
    if (h < Hr - 1) { float2 a = *(float2*)&g_PQK[rowp + (size_t)Wr * 192 + 96 + 64 + c0]; k.x += a.x; k.y += a.y; }
    k.x = fmaxf(fmaf(k.x, g_ksc[c0], g_kof[c0]), 0.f);
    k.y = fmaxf(fmaf(k.y, g_ksc[c0 + 1], g_kof[c0 + 1]), 0.f);
    g_K16h[(size_t)(pb + n) * 16 + cp] = pack2(k.x, k.y);
    g_K16l[(size_t)(pb + n) * 16 + cp] = pack2(k.x - f16r(k.x), k.y - f16r(k.y));
}

// ------------------- fp16 tensor-core flash attention, 64 q-rows/CTA
// Double-buffered cp.async K/V pipeline. S = split-fp16 x3; PV = plain fp16.
// smem offsets in u32 units:
#define OQH 0
#define OQL 1280
#define OKH 2560       // 2 stages x 640
#define OKL 3840       // 2 stages x 640
#define OVS 5120       // 2 stages x 5120
#define OPS 15360      // 64 x 33
#define OP16 17472     // 64 x 20
#define OSTAT 18752    // 3*64 stats + 64 pas
#define ASMEM ((18752 + 256) * 4)

__global__ __launch_bounds__(256, 2) void attn(const float* __restrict__ gamma,
                                               float* __restrict__ out, int inst0) {
    extern __shared__ u32 sm32[];
    u32* Qh = sm32 + OQH;
    u32* Ql = sm32 + OQL;
    float* Ps  = (float*)(sm32 + OPS);
    u32* Ps16 = sm32 + OP16;
    float* rmax = (float*)(sm32 + OSTAT);
    float* rsum = rmax + 64;
    float* rscale = rsum + 64;
    int* pas = (int*)(rscale + 64);
    float* stage = (float*)(sm32 + OVS);   // epilogue union over V buffers

    u32 smb = (u32)__cvta_generic_to_shared(sm32);

    int inst = inst0 + blockIdx.y;
    int region = inst >> 3, b = inst & 7;
    int N = c_N[region];
    int n0 = blockIdx.x * 64;
    if (n0 >= N) return;
    int pb = c_base[region] + b * N;

    int tid = threadIdx.x;
    int lane = tid & 31, w = tid >> 5;
    int g = lane >> 2, t = lane & 3;
    if (tid < 64) {
        rmax[tid] = -1e30f; rsum[tid] = 0.f;
        pas[tid] = g_pix[pb + n0 + tid];
    }
    {   // Q tile hi/lo: 64 rows x 4 float4 each
        int row = tid >> 2, c4 = tid & 3;
        *(float4*)&Qh[row * 20 + c4 * 4] = *(const float4*)&g_Q16h[(size_t)(pb + n0 + row) * 16 + c4 * 4];
        *(float4*)&Ql[row * 20 + c4 * 4] = *(const float4*)&g_Q16l[(size_t)(pb + n0 + row) * 16 + c4 * 4];
    }

    // per-thread prefetch addressing (constant across tiles)
    int krow = (tid & 127) >> 2, kc4 = tid & 3;
    const u32* ksrc = (tid < 128) ? g_K16h : g_K16l;
    u32 kdstoff = ((tid < 128) ? OKH : OKL) + krow * 20 + kc4 * 4;

    int mt = w & 3, ntk = w >> 2;             // S mapping
    int wm = w & 3, wslab = (w >> 2) * 128;   // PV mapping

    float acc[16][4];
#pragma unroll
    for (int nt = 0; nt < 16; nt++)
#pragma unroll
        for (int r = 0; r < 4; r++) acc[nt][r] = 0.f;

    int nmt = N >> 5;
    // prologue: prefetch tile 0 into stage 0
    {
        int mb = pb;
        cpa16(smb + (kdstoff + 0 * 640) * 4, &ksrc[(size_t)(mb + krow) * 16 + kc4 * 4]);
        size_t vbase = (size_t)(mb >> 5) * 4096;
#pragma unroll
        for (int r = 0; r < 4; r++) {
            int idx = tid + r * 256;
            int ch = idx >> 2, c4 = idx & 3;
            cpa16(smb + (OVS + 0 * 5120 + ch * 20 + c4 * 4) * 4, &g_V16[vbase + ch * 16 + c4 * 4]);
        }
        CPA_COMMIT;
    }

    for (int it = 0; it < nmt; it++) {
        int s = it & 1;
        int kb = s * 640, vb = s * 5120;
        __syncthreads();                       // all readers of stage s^1 done
        if (it + 1 < nmt) {                    // prefetch next tile into stage s^1
            int mb = pb + (it + 1) * 32;
            int s2 = (it + 1) & 1;
            cpa16(smb + (kdstoff + s2 * 640) * 4, &ksrc[(size_t)(mb + krow) * 16 + kc4 * 4]);
            size_t vbase = (size_t)(mb >> 5) * 4096;
#pragma unroll
            for (int r = 0; r < 4; r++) {
                int idx = tid + r * 256;
                int ch = idx >> 2, c4 = idx & 3;
                cpa16(smb + (OVS + s2 * 5120 + ch * 20 + c4 * 4) * 4, &g_V16[vbase + ch * 16 + c4 * 4]);
            }
            CPA_COMMIT;
            CPA_WAIT1;                         // tile `it` complete
        } else {
            CPA_WAIT0;
        }
        __syncthreads();                       // loads visible to all
        u32* Kh = sm32 + OKH + kb;
        u32* Kl = sm32 + OKL + kb;
        u32* Vs = sm32 + OVS + vb;
        {   // S: split-fp16, warp does 16 rows x 16 keys
            float sacc[2][4] = {{0.f,0.f,0.f,0.f},{0.f,0.f,0.f,0.f}};
#pragma unroll
            for (int kt = 0; kt < 2; kt++) {
                int ar = (mt * 16 + g) * 20 + kt * 8 + t;
                u32 ah0 = Qh[ar], ah1 = Qh[ar + 160], ah2 = Qh[ar + 4], ah3 = Qh[ar + 164];
                u32 al0 = Ql[ar], al1 = Ql[ar + 160], al2 = Ql[ar + 4], al3 = Ql[ar + 164];
#pragma unroll
                for (int sub = 0; sub < 2; sub++) {
                    int kr = (ntk * 16 + sub * 8 + g) * 20 + kt * 8 + t;
                    u32 bh0 = Kh[kr], bh1 = Kh[kr + 4];
                    u32 bl0 = Kl[kr], bl1 = Kl[kr + 4];
                    MMA_F16(sacc[sub], ah0, ah1, ah2, ah3, bh0, bh1);
                    MMA_F16(sacc[sub], al0, al1, al2, al3, bh0, bh1);
                    MMA_F16(sacc[sub], ah0, ah1, ah2, ah3, bl0, bl1);
                }
            }
#pragma unroll
            for (int sub = 0; sub < 2; sub++) {
                int pc = ntk * 16 + sub * 8 + 2 * t;
                int pr0 = (mt * 16 + g) * 33 + pc;
                int pr8 = pr0 + 8 * 33;
                Ps[pr0]     = sacc[sub][0];
                Ps[pr0 + 1] = sacc[sub][1];
                Ps[pr8]     = sacc[sub][2];
                Ps[pr8 + 1] = sacc[sub][3];
            }
        }
        __syncthreads();
        {   // online softmax: 4 threads/row, 8 keys each; write fp16 pairs
            int r = tid >> 2, qt = tid & 3;
            float* prow = &Ps[r * 33 + qt * 8];
            float p[8];
#pragma unroll
            for (int j = 0; j < 8; j++) p[j] = prow[j];
            float mx0 = rmax[r];
            float ml = p[0];
#pragma unroll
            for (int j = 1; j < 8; j++) ml = fmaxf(ml, p[j]);
            ml = fmaxf(ml, __shfl_xor_sync(0xffffffffu, ml, 1));
            ml = fmaxf(ml, __shfl_xor_sync(0xffffffffu, ml, 2));
            float nm = fmaxf(mx0, ml);
            float s2 = 0.f;
#pragma unroll
            for (int j = 0; j < 8; j++) {
                p[j] = __expf(p[j] - nm);
                s2 += p[j];
            }
            u32* p16 = &Ps16[r * 20 + qt * 4];
            p16[0] = pack2(p[0], p[1]);
            p16[1] = pack2(p[2], p[3]);
            p16[2] = pack2(p[4], p[5]);
            p16[3] = pack2(p[6], p[7]);
            s2 += __shfl_xor_sync(0xffffffffu, s2, 1);
            s2 += __shfl_xor_sync(0xffffffffu, s2, 2);
            if (qt == 0) {
                float sc = __expf(mx0 - nm);
                rsum[r] = rsum[r] * sc + s2;
                rmax[r] = nm;
                rscale[r] = sc;
            }
        }
        __syncthreads();
        {   // rescale + PV fp16 MMA (warp: 16 rows x 128 ch)
            float sc0 = rscale[wm * 16 + g];
            float sc1 = rscale[wm * 16 + g + 8];
#pragma unroll
            for (int nt = 0; nt < 16; nt++) {
                acc[nt][0] *= sc0; acc[nt][1] *= sc0;
                acc[nt][2] *= sc1; acc[nt][3] *= sc1;
            }
#pragma unroll
            for (int kt = 0; kt < 2; kt++) {
                int pr = (wm * 16 + g) * 20 + kt * 8 + t;
                u32 pa0 = Ps16[pr], pa1 = Ps16[pr + 160], pa2 = Ps16[pr + 4], pa3 = Ps16[pr + 164];
#pragma unroll
                for (int nt = 0; nt < 16; nt++) {
                    int vr = (wslab + nt * 8 + g) * 20 + kt * 8 + t;
                    MMA_F16(acc[nt], pa0, pa1, pa2, pa3, Vs[vr], Vs[vr + 4]);
                }
            }
        }
    }
    // epilogue: two passes of 32 rows staged, then coalesced RMW
    float gm = 0.5f * gamma[0];
#pragma unroll
    for (int pass = 0; pass < 2; pass++) {
        __syncthreads();
        if ((wm >> 1) == pass) {
            float f0 = gm / rsum[wm * 16 + g];
            float f1 = gm / rsum[wm * 16 + g + 8];
            int row0 = (wm * 16 + g) - pass * 32;
            int r0 = row0 * 264 + wslab + 2 * t;
            int r8 = (row0 + 8) * 264 + wslab + 2 * t;
#pragma unroll
            for (int nt = 0; nt < 16; nt++) {
                stage[r0 + nt * 8]     = acc[nt][0] * f0;
                stage[r0 + nt * 8 + 1] = acc[nt][1] * f0;
                stage[r8 + nt * 8]     = acc[nt][2] * f1;
                stage[r8 + nt * 8 + 1] = acc[nt][3] * f1;
            }
        }
        __syncthreads();
        int tn = tid & 7, tc = tid >> 3;
#pragma unroll
        for (int i = 0; i < 4; i++) {
            int row = tn + 8 * i;
            int pa = pas[pass * 32 + row];
#pragma unroll
            for (int j = 0; j < 8; j++) {
                int c = tc * 8 + j;
                out[pa + c * HW] += stage[row * 264 + c];
            }
        }
    }
}

// ---------------------------------------------------------------- launcher
extern "C" void kernel_launch(void* const* d_in, const int* in_sizes, int n_in,
                              void* d_out, int out_size) {
    const float* x   = (const float*)d_in[0];
    const float* Wq  = (const float*)d_in[1];
    const float* bq  = (const float*)d_in[2];
    const float* q_s = (const float*)d_in[3];
    const float* q_o = (const float*)d_in[4];
    const float* q_m = (const float*)d_in[5];
    const float* q_v = (const float*)d_in[6];
    const float* Wk  = (const float*)d_in[7];
    const float* bk  = (const float*)d_in[8];
    const float* k_s = (const float*)d_in[9];
    const float* k_o = (const float*)d_in[10];
    const float* k_m = (const float*)d_in[11];
    const float* k_v = (const float*)d_in[12];
    const float* Wv  = (const float*)d_in[13];
    const float* bv  = (const float*)d_in[14];
    const float* gam = (const float*)d_in[15];
    float* out = (float*)d_out;

    cudaFuncSetAttribute(attn, cudaFuncAttributeMaxDynamicSharedMemorySize, ASMEM);

    prep_wall<<<224, 256>>>(Wq, Wk, Wv);
    prep_bn<<<1, 32>>>(bq, q_s, q_o, q_m, q_v, bk, k_s, k_o, k_m, k_v);
    prep_pix<<<dim3(6, 232), 256>>>();
    copy_x<<<4096, 256>>>((const float4*)x, (float4*)out);
    qkv_gemm<<<dim3(7, 24, 232), 256>>>(x, bv);
    v_pack<<<TOTPIX / 32, 256>>>();
    combine_qk<<<dim3(96, 232), 256>>>();
    // win regions (0..11): disjoint pixels within launch -> plain RMW
    attn<<<dim3(16, 96), 256, ASMEM>>>(gam, out, 0);
    // shift regions (12..28): partition of image -> plain RMW
    attn<<<dim3(24, 136), 256, ASMEM>>>(gam, out, 96);
}

// round 10
// speedup vs baseline: 3.0078x; 1.0938x over previous
#include <cuda_runtime.h>
#include <cuda_fp16.h>
#include <math.h>
#include <stdint.h>

// Problem constants (B=8, C=256, H=W=128, win_n=4, shift=16)
#define HW   16384
#define IMG  128
#define NREG 29
#define TOTPIX 229376
#define COUT 448        // 256 V + 96 Pq(3 taps x 32) + 96 Pk

typedef uint32_t u32;

__device__ __forceinline__ float f16r(float v) {
    return __half2float(__float2half_rn(v));
}
__device__ __forceinline__ u32 pack2(float e0, float e1) {   // e0 -> lo half
    __half2 h = __floats2half2_rn(e0, e1);
    return *reinterpret_cast<u32*>(&h);
}

// m16n8k16 fp16 MMA, fp32 accumulate
#define MMA_F16(d, a0, a1, a2, a3, b0, b1)                                           \
    asm volatile("mma.sync.aligned.m16n8k16.row.col.f32.f16.f16.f32 "                \
                 "{%0,%1,%2,%3},{%4,%5,%6,%7},{%8,%9},{%0,%1,%2,%3};"                \
                 : "+f"(d[0]), "+f"(d[1]), "+f"(d[2]), "+f"(d[3])                    \
                 : "r"(a0), "r"(a1), "r"(a2), "r"(a3), "r"(b0), "r"(b1))

__device__ __forceinline__ void cpa16(u32 dst, const u32* src) {
    asm volatile("cp.async.cg.shared.global [%0], [%1], 16;" :: "r"(dst), "l"(src));
}
#define CPA_COMMIT asm volatile("cp.async.commit_group;")
#define CPA_WAIT1  asm volatile("cp.async.wait_group 1;")
#define CPA_WAIT0  asm volatile("cp.async.wait_all;")

// Region tables: 12 win (rows 1..3 x cols 0..3), 9 shift-inner, 8 borders
__constant__ int c_h0[NREG] = {32,32,32,32, 64,64,64,64, 96,96,96,96,
                               16,16,16, 48,48,48, 80,80,80,
                               0,0,0, 16,16, 112,112,112};
__constant__ int c_w0[NREG] = {0,32,64,96, 0,32,64,96, 0,32,64,96,
                               16,48,80, 16,48,80, 16,48,80,
                               0,16,112, 0,112, 0,16,112};
__constant__ int c_Hr[NREG] = {32,32,32,32,32,32,32,32,32,32,32,32,
                               32,32,32,32,32,32,32,32,32,
                               16,16,16, 96,96, 16,16,16};
__constant__ int c_Wr[NREG] = {32,32,32,32,32,32,32,32,32,32,32,32,
                               32,32,32,32,32,32,32,32,32,
                               16,96,16, 16,16, 16,96,16};
__constant__ int c_N[NREG]  = {1024,1024,1024,1024,1024,1024,1024,1024,1024,1024,1024,1024,
                               1024,1024,1024,1024,1024,1024,1024,1024,1024,
                               256,1536,256, 1536,1536, 256,1536,256};
__constant__ int c_base[NREG] = {0,8192,16384,24576,32768,40960,49152,57344,65536,73728,81920,90112,
                                 98304,106496,114688,122880,131072,139264,147456,155648,163840,
                                 172032,174080,186368, 188416,200704, 212992,215040,227328};

// Scratch (__device__ globals)
static __device__ u32   g_W16h[COUT * 128];                  // [co][ci-pair] fp16x2 hi
static __device__ u32   g_W16l[COUT * 128];                  // lo residual
static __device__ u32   g_V16a[(size_t)TOTPIX * 128];        // [pix][ch-pair] fp16x2
static __device__ u32   g_V16 [(size_t)TOTPIX * 128];        // [tile32][ch][key-pair]
static __device__ float g_PQK[(size_t)TOTPIX * 192];
static __device__ u32   g_Q16h[(size_t)TOTPIX * 16];         // [pix][d-pair]
static __device__ u32   g_Q16l[(size_t)TOTPIX * 16];
static __device__ u32   g_K16h[(size_t)TOTPIX * 16];
static __device__ u32   g_K16l[(size_t)TOTPIX * 16];
static __device__ int   g_pix[TOTPIX];
static __device__ float g_qsc[32], g_qof[32], g_ksc[32], g_kof[32];

// ---------------------------------------------------------------- prep kernels
__device__ __forceinline__ float wall_val(const float* Wq, const float* Wk,
                                          const float* Wv, int co, int ci) {
    if (co < 256) return Wv[co * 256 + ci];
    if (co < 352) { int t = (co - 256) >> 5, c8 = (co - 256) & 31;
                    return Wq[(c8 * 256 + ci) * 3 + t]; }
    { int t = (co - 352) >> 5, c8 = (co - 352) & 31;
      return Wk[(c8 * 256 + ci) * 3 + t]; }
}

__global__ void prep_wall(const float* __restrict__ Wq, const float* __restrict__ Wk,
                          const float* __restrict__ Wv) {
    int idx = blockIdx.x * 256 + threadIdx.x;
    if (idx >= COUT * 128) return;
    int co = idx >> 7, cp = idx & 127;
    float v0 = wall_val(Wq, Wk, Wv, co, 2 * cp);
    float v1 = wall_val(Wq, Wk, Wv, co, 2 * cp + 1);
    g_W16h[idx] = pack2(v0, v1);
    g_W16l[idx] = pack2(v0 - f16r(v0), v1 - f16r(v1));
}

__global__ void prep_bn(const float* bq, const float* qs, const float* qo, const float* qm, const float* qv,
                        const float* bk, const float* ks, const float* ko, const float* km, const float* kv) {
    int c = threadIdx.x;
    if (c >= 32) return;
    float sc = qs[c] * rsqrtf(qv[c] + 1e-5f);
    g_qsc[c] = sc;
    g_qof[c] = bq[c] * sc + qo[c] - qm[c] * sc;
    sc = ks[c] * rsqrtf(kv[c] + 1e-5f);
    g_ksc[c] = sc;
    g_kof[c] = bk[c] * sc + ko[c] - km[c] * sc;
}

__global__ void prep_pix() {
    int inst = blockIdx.y;
    int region = inst >> 3, b = inst & 7;
    int N = c_N[region];
    int n = blockIdx.x * 256 + threadIdx.x;
    if (n >= N) return;
    int Wr = c_Wr[region];
    int h = n / Wr, w = n - h * Wr;
    g_pix[c_base[region] + b * N + n] = b * (256 * HW) + (c_h0[region] + h) * IMG + c_w0[region] + w;
}

__global__ void copy_x(const float4* __restrict__ x, float4* __restrict__ o) {
    int i = blockIdx.x * blockDim.x + threadIdx.x;
    int stride = gridDim.x * blockDim.x;
    for (; i < 8388608; i += stride) o[i] = x[i];
}

// ---------------- QKV GEMM: [pix,256]@[256,448]
// V-column tiles (n0 < 256): plain fp16 (1 MMA).  Q/K tap tiles: split-fp16 x3.
__global__ __launch_bounds__(256) void qkv_gemm(const float* __restrict__ x,
                                                const float* __restrict__ bv) {
    int inst = blockIdx.z;
    int region = inst >> 3, b = inst & 7;
    int N = c_N[region];
    int m0 = blockIdx.y * 64;
    if (m0 >= N) return;
    int pb = c_base[region] + b * N;
    int n0 = blockIdx.x * 64;
    bool vt = (n0 < 256);          // pure-V tile: plain fp16

    __shared__ __align__(16) u32 Ah[64 * 20], Al[64 * 20];
    __shared__ __align__(16) u32 Bh[64 * 20], Bl[64 * 20];
    __shared__ int pas[64];

    int tid = threadIdx.x;
    if (tid < 64) pas[tid] = g_pix[pb + m0 + tid];
    __syncthreads();

    int lane = tid & 31, w = tid >> 5;
    int g = lane >> 2, t = lane & 3;
    int mt = w & 3, ntq = w >> 2;

    float acc[4][4];
#pragma unroll
    for (int i = 0; i < 4; i++)
#pragma unroll
        for (int j = 0; j < 4; j++) acc[i][j] = 0.f;

    for (int k0 = 0; k0 < 256; k0 += 32) {
        __syncthreads();
#pragma unroll
        for (int r = 0; r < 4; r++) {              // A: 64 m x 16 k-pairs
            int idx = tid + r * 256;
            int m = idx & 63, kp = idx >> 6;
            float v0 = x[pas[m] + (k0 + 2 * kp) * HW];
            float v1 = x[pas[m] + (k0 + 2 * kp + 1) * HW];
            Ah[m * 20 + kp] = pack2(v0, v1);
            if (!vt) Al[m * 20 + kp] = pack2(v0 - f16r(v0), v1 - f16r(v1));
        }
        {                                          // B: 64 n x 16 k-pairs
            int n = tid >> 2, c4 = tid & 3;
            *(float4*)&Bh[n * 20 + c4 * 4] = *(const float4*)&g_W16h[(size_t)(n0 + n) * 128 + k0 / 2 + c4 * 4];
            if (!vt)
                *(float4*)&Bl[n * 20 + c4 * 4] = *(const float4*)&g_W16l[(size_t)(n0 + n) * 128 + k0 / 2 + c4 * 4];
        }
        __syncthreads();
#pragma unroll
        for (int kt = 0; kt < 2; kt++) {
            int ar = (mt * 16 + g) * 20 + kt * 8 + t;
            u32 ah0 = Ah[ar], ah1 = Ah[ar + 160], ah2 = Ah[ar + 4], ah3 = Ah[ar + 164];
#pragma unroll
            for (int ns = 0; ns < 4; ns++) {
                int nr = (ntq * 32 + ns * 8 + g) * 20 + kt * 8 + t;
                u32 bh0 = Bh[nr], bh1 = Bh[nr + 4];
                MMA_F16(acc[ns], ah0, ah1, ah2, ah3, bh0, bh1);
                if (!vt) {
                    u32 al0 = Al[ar], al1 = Al[ar + 160], al2 = Al[ar + 4], al3 = Al[ar + 164];
                    u32 bl0 = Bl[nr], bl1 = Bl[nr + 4];
                    MMA_F16(acc[ns], al0, al1, al2, al3, bh0, bh1);
                    MMA_F16(acc[ns], ah0, ah1, ah2, ah3, bl0, bl1);
                }
            }
        }
    }
#pragma unroll
    for (int ns = 0; ns < 4; ns++) {
        int co = n0 + ntq * 32 + ns * 8 + 2 * t;
        size_t mg  = (size_t)(pb + m0 + mt * 16 + g);
        size_t mg8 = mg + 8;
        if (co < 256) {
            float b0 = bv[co], b1 = bv[co + 1];
            g_V16a[mg  * 128 + co / 2] = pack2(acc[ns][0] + b0, acc[ns][1] + b1);
            g_V16a[mg8 * 128 + co / 2] = pack2(acc[ns][2] + b0, acc[ns][3] + b1);
        } else {
            int cp = co - 256;
            g_PQK[mg  * 192 + cp]     = acc[ns][0];
            g_PQK[mg  * 192 + cp + 1] = acc[ns][1];
            g_PQK[mg8 * 192 + cp]     = acc[ns][2];
            g_PQK[mg8 * 192 + cp + 1] = acc[ns][3];
        }
    }
}

// ---------------- V transpose/pack: [pix][ch-pair] -> [tile32][ch][key-pair]
__global__ __launch_bounds__(256) void v_pack() {
    __shared__ u32 Vt[32 * 129];
    int tile = blockIdx.x;
    int tid = threadIdx.x;
    size_t base = (size_t)tile * 4096;
#pragma unroll
    for (int r = 0; r < 16; r++) {
        int idx = tid + r * 256;
        Vt[(idx >> 7) * 129 + (idx & 127)] = g_V16a[base + idx];
    }
    __syncthreads();
#pragma unroll
    for (int r = 0; r < 8; r++) {
        int idx = tid + r * 256;
        int cp = idx >> 4, kp = idx & 15;
        u32 a = Vt[(2 * kp) * 129 + cp];
        u32 b = Vt[(2 * kp + 1) * 129 + cp];
        g_V16[base + (size_t)(2 * cp) * 16 + kp]     = __byte_perm(a, b, 0x5410);
        g_V16[base + (size_t)(2 * cp + 1) * 16 + kp] = __byte_perm(a, b, 0x7632);
    }
}

// ------------- combine conv taps + BN + ReLU, split Q/K into fp16 hi/lo pairs
__global__ void combine_qk() {
    int inst = blockIdx.y;
    int region = inst >> 3, b = inst & 7;
    int N = c_N[region];
    int idx = blockIdx.x * 256 + threadIdx.x;
    int n = idx >> 4;
    if (n >= N) return;
    int cp = idx & 15, c0 = 2 * cp;
    int Wr = c_Wr[region], Hr = c_Hr[region];
    int pb = c_base[region] + b * N;
    int h = n / Wr, w = n - h * Wr;
    size_t rowp = (size_t)(pb + n) * 192;

    float2 q = *(float2*)&g_PQK[rowp + 32 + c0];
    if (w > 0)      { float2 a = *(float2*)&g_PQK[rowp - 192 + c0]; q.x += a.x; q.y += a.y; }
    if (w < Wr - 1) { float2 a = *(float2*)&g_PQK[rowp + 192 + 64 + c0]; q.x += a.x; q.y += a.y; }
    q.x = fmaxf(fmaf(q.x, g_qsc[c0], g_qof[c0]), 0.f);
    q.y = fmaxf(fmaf(q.y, g_qsc[c0 + 1], g_qof[c0 + 1]), 0.f);
    g_Q16h[(size_t)(pb + n) * 16 + cp] = pack2(q.x, q.y);
    g_Q16l[(size_t)(pb + n) * 16 + cp] = pack2(q.x - f16r(q.x), q.y - f16r(q.y));

    float2 k = *(float2*)&g_PQK[rowp + 96 + 32 + c0];
    if (h > 0)      { float2 a = *(float2*)&g_PQK[rowp - (size_t)Wr * 192 + 96 + c0]; k.x += a.x; k.y += a.y; }
    if (h < Hr - 1) { float2 a = *(float2*)&g_PQK[rowp + (size_t)Wr * 192 + 96 + 64 + c0]; k.x += a.x; k.y += a.y; }
    k.x = fmaxf(fmaf(k.x, g_ksc[c0], g_kof[c0]), 0.f);
    k.y = fmaxf(fmaf(k.y, g_ksc[c0 + 1], g_kof[c0 + 1]), 0.f);
    g_K16h[(size_t)(pb + n) * 16 + cp] = pack2(k.x, k.y);
    g_K16l[(size_t)(pb + n) * 16 + cp] = pack2(k.x - f16r(k.x), k.y - f16r(k.y));
}

// ------------------- fp16 flash attention, 64 q-rows x 64-key tiles
// Register-resident softmax (shfl reductions + tiny cross-warp exchange);
// Q fragments in registers; double-buffered cp.async K/V.
// smem offsets in u32 units:
#define OKH 0          // 2 stages x 64x20
#define OKL 2560
#define OVS 5120       // 2 stages x 256x36
#define OP16 23552     // 64 x 36
#define OWM 25856      // wmax [2][64]
#define OWS 25984      // wsum [2][64]
#define OSTAT 26112    // rmax/rsum/rscale/pas 4x64
#define ASMEM (26368 * 4)

__global__ __launch_bounds__(256, 2) void attn(const float* __restrict__ gamma,
                                               float* __restrict__ out, int inst0) {
    extern __shared__ u32 sm32[];
    u32* Ps16 = sm32 + OP16;
    float* wmax = (float*)(sm32 + OWM);
    float* wsum = (float*)(sm32 + OWS);
    float* rmax = (float*)(sm32 + OSTAT);
    float* rsum = rmax + 64;
    float* rscale = rsum + 64;
    int* pas = (int*)(rscale + 64);
    float* stage = (float*)(sm32 + OVS);   // epilogue union over V buffers

    u32 smb = (u32)__cvta_generic_to_shared(sm32);

    int inst = inst0 + blockIdx.y;
    int region = inst >> 3, b = inst & 7;
    int N = c_N[region];
    int n0 = blockIdx.x * 64;
    if (n0 >= N) return;
    int pb = c_base[region] + b * N;

    int tid = threadIdx.x;
    int lane = tid & 31, w = tid >> 5;
    int g = lane >> 2, t = lane & 3;
    if (tid < 64) {
        rmax[tid] = -1e30f; rsum[tid] = 0.f;
        pas[tid] = g_pix[pb + n0 + tid];
    }

    int mt = w & 3, ntk = w >> 2;             // S mapping: rows mt*16, keys ntk*32
    int wm = w & 3, wslab = (w >> 2) * 128;   // PV mapping
    int rowg = mt * 16 + g;

    // Q fragments hi/lo in registers (fixed per CTA)
    u32 aqh[2][4], aql[2][4];
    {
        size_t r0 = (size_t)(pb + n0 + rowg) * 16;
        size_t r8 = r0 + 128;   // +8 rows * 16
#pragma unroll
        for (int kt = 0; kt < 2; kt++) {
            int c = kt * 8 + t;
            aqh[kt][0] = g_Q16h[r0 + c];     aqh[kt][1] = g_Q16h[r8 + c];
            aqh[kt][2] = g_Q16h[r0 + c + 4]; aqh[kt][3] = g_Q16h[r8 + c + 4];
            aql[kt][0] = g_Q16l[r0 + c];     aql[kt][1] = g_Q16l[r8 + c];
            aql[kt][2] = g_Q16l[r0 + c + 4]; aql[kt][3] = g_Q16l[r8 + c + 4];
        }
    }

    // prefetch addressing
    int kidx = tid & 127;
    const u32* ksrc = (tid < 128) ? g_K16h : g_K16l;
    u32 kdst = (tid < 128) ? (u32)OKH : (u32)OKL;

    float acc[16][4];
#pragma unroll
    for (int nt = 0; nt < 16; nt++)
#pragma unroll
        for (int r = 0; r < 4; r++) acc[nt][r] = 0.f;

    int nmt = N >> 6;
    // prologue: prefetch tile 0 into stage 0
    {
        int mb = pb;
#pragma unroll
        for (int r = 0; r < 2; r++) {
            int chunk = kidx + r * 128;
            int krow = chunk >> 2, kc4 = chunk & 3;
            cpa16(smb + (kdst + krow * 20 + kc4 * 4) * 4, &ksrc[(size_t)(mb + krow) * 16 + kc4 * 4]);
        }
        size_t vbase = (size_t)(mb >> 5) * 4096;
#pragma unroll
        for (int r = 0; r < 8; r++) {
            int idx = tid + r * 256;
            int ch = idx >> 3, sub = idx & 7;
            int half = sub >> 2, c4 = sub & 3;
            cpa16(smb + (OVS + ch * 36 + half * 16 + c4 * 4) * 4,
                  &g_V16[vbase + (size_t)half * 4096 + ch * 16 + c4 * 4]);
        }
        CPA_COMMIT;
    }

    for (int it = 0; it < nmt; it++) {
        int s = it & 1;
        __syncthreads();                       // readers of stage s^1 done
        if (it + 1 < nmt) {
            int mb = pb + (it + 1) * 64;
            int s2 = (it + 1) & 1;
#pragma unroll
            for (int r = 0; r < 2; r++) {
                int chunk = kidx + r * 128;
                int krow = chunk >> 2, kc4 = chunk & 3;
                cpa16(smb + (kdst + s2 * 1280 + krow * 20 + kc4 * 4) * 4,
                      &ksrc[(size_t)(mb + krow) * 16 + kc4 * 4]);
            }
            size_t vbase = (size_t)(mb >> 5) * 4096;
#pragma unroll
            for (int r = 0; r < 8; r++) {
                int idx = tid + r * 256;
                int ch = idx >> 3, sub = idx & 7;
                int half = sub >> 2, c4 = sub & 3;
                cpa16(smb + (OVS + s2 * 9216 + ch * 36 + half * 16 + c4 * 4) * 4,
                      &g_V16[vbase + (size_t)half * 4096 + ch * 16 + c4 * 4]);
            }
            CPA_COMMIT;
            CPA_WAIT1;
        } else {
            CPA_WAIT0;
        }
        __syncthreads();                       // tile data visible
        u32* Kh = sm32 + OKH + s * 1280;
        u32* Kl = sm32 + OKL + s * 1280;
        u32* Vs = sm32 + OVS + s * 9216;

        // ---- S: split-fp16, warp does 16 rows x 32 keys (registers)
        float sacc[4][4];
#pragma unroll
        for (int i = 0; i < 4; i++)
#pragma unroll
            for (int j = 0; j < 4; j++) sacc[i][j] = 0.f;
#pragma unroll
        for (int kt = 0; kt < 2; kt++) {
            u32 ah0 = aqh[kt][0], ah1 = aqh[kt][1], ah2 = aqh[kt][2], ah3 = aqh[kt][3];
            u32 al0 = aql[kt][0], al1 = aql[kt][1], al2 = aql[kt][2], al3 = aql[kt][3];
#pragma unroll
            for (int sub = 0; sub < 4; sub++) {
                int kr = (ntk * 32 + sub * 8 + g) * 20 + kt * 8 + t;
                u32 bh0 = Kh[kr], bh1 = Kh[kr + 4];
                u32 bl0 = Kl[kr], bl1 = Kl[kr + 4];
                MMA_F16(sacc[sub], ah0, ah1, ah2, ah3, bh0, bh1);
                MMA_F16(sacc[sub], al0, al1, al2, al3, bh0, bh1);
                MMA_F16(sacc[sub], ah0, ah1, ah2, ah3, bl0, bl1);
            }
        }
        // ---- softmax phase A: warp-local row max over 32 keys
        float m0 = fmaxf(fmaxf(sacc[0][0], sacc[0][1]), fmaxf(sacc[1][0], sacc[1][1]));
        m0 = fmaxf(m0, fmaxf(fmaxf(sacc[2][0], sacc[2][1]), fmaxf(sacc[3][0], sacc[3][1])));
        float m1 = fmaxf(fmaxf(sacc[0][2], sacc[0][3]), fmaxf(sacc[1][2], sacc[1][3]));
        m1 = fmaxf(m1, fmaxf(fmaxf(sacc[2][2], sacc[2][3]), fmaxf(sacc[3][2], sacc[3][3])));
        m0 = fmaxf(m0, __shfl_xor_sync(0xffffffffu, m0, 1));
        m0 = fmaxf(m0, __shfl_xor_sync(0xffffffffu, m0, 2));
        m1 = fmaxf(m1, __shfl_xor_sync(0xffffffffu, m1, 1));
        m1 = fmaxf(m1, __shfl_xor_sync(0xffffffffu, m1, 2));
        float rm0 = rmax[rowg], rm1 = rmax[rowg + 8];
        if (t == 0) {
            wmax[ntk * 64 + rowg]     = m0;
            wmax[ntk * 64 + rowg + 8] = m1;
        }
        __syncthreads();                       // wmax visible
        // ---- softmax phase B: exp in registers, pack to Ps16
        float nm0 = fmaxf(rm0, fmaxf(wmax[rowg], wmax[64 + rowg]));
        float nm1 = fmaxf(rm1, fmaxf(wmax[rowg + 8], wmax[64 + rowg + 8]));
        float s0 = 0.f, s1 = 0.f;
#pragma unroll
        for (int sub = 0; sub < 4; sub++) {
            float p00 = __expf(sacc[sub][0] - nm0);
            float p01 = __expf(sacc[sub][1] - nm0);
            float p10 = __expf(sacc[sub][2] - nm1);
            float p11 = __expf(sacc[sub][3] - nm1);
            s0 += p00 + p01; s1 += p10 + p11;
            int kp = ntk * 16 + sub * 4 + t;
            Ps16[rowg * 36 + kp]       = pack2(p00, p01);
            Ps16[(rowg + 8) * 36 + kp] = pack2(p10, p11);
        }
        s0 += __shfl_xor_sync(0xffffffffu, s0, 1);
        s0 += __shfl_xor_sync(0xffffffffu, s0, 2);
        s1 += __shfl_xor_sync(0xffffffffu, s1, 1);
        s1 += __shfl_xor_sync(0xffffffffu, s1, 2);
        if (t == 0) {
            wsum[ntk * 64 + rowg]     = s0;
            wsum[ntk * 64 + rowg + 8] = s1;
            if (ntk == 0) {
                rscale[rowg]     = __expf(rm0 - nm0);
                rscale[rowg + 8] = __expf(rm1 - nm1);
                rmax[rowg] = nm0; rmax[rowg + 8] = nm1;
            }
        }
        __syncthreads();                       // Ps16 + rscale + wsum visible
        // ---- PV: rescale + fp16 MMA (warp: 16 rows x 128 ch, 64 keys)
        {
            float sc0 = rscale[wm * 16 + g];
            float sc1 = rscale[wm * 16 + g + 8];
#pragma unroll
            for (int nt = 0; nt < 16; nt++) {
                acc[nt][0] *= sc0; acc[nt][1] *= sc0;
                acc[nt][2] *= sc1; acc[nt][3] *= sc1;
            }
#pragma unroll
            for (int kt = 0; kt < 4; kt++) {
                int pr = (wm * 16 + g) * 36 + kt * 8 + t;
                u32 pa0 = Ps16[pr], pa1 = Ps16[pr + 288], pa2 = Ps16[pr + 4], pa3 = Ps16[pr + 292];
#pragma unroll
                for (int nt = 0; nt < 16; nt++) {
                    int vr = (wslab + nt * 8 + g) * 36 + kt * 8 + t;
                    MMA_F16(acc[nt], pa0, pa1, pa2, pa3, Vs[vr], Vs[vr + 4]);
                }
            }
        }
        // running-sum update (rsum read only at epilogue)
        if (w < 4 && lane < 16) {
            int row = w * 16 + lane;
            rsum[row] = rsum[row] * rscale[row] + wsum[row] + wsum[64 + row];
        }
    }
    // epilogue: two passes of 32 rows staged, then coalesced RMW
    float gm = 0.5f * gamma[0];
#pragma unroll
    for (int pass = 0; pass < 2; pass++) {
        __syncthreads();
        if ((wm >> 1) == pass) {
            float f0 = gm / rsum[wm * 16 + g];
            float f1 = gm / rsum[wm * 16 + g + 8];
            int row0 = (wm * 16 + g) - pass * 32;
            int r0 = row0 * 264 + wslab + 2 * t;
            int r8 = (row0 + 8) * 264 + wslab + 2 * t;
#pragma unroll
            for (int nt = 0; nt < 16; nt++) {
                stage[r0 + nt * 8]     = acc[nt][0] * f0;
                stage[r0 + nt * 8 + 1] = acc[nt][1] * f0;
                stage[r8 + nt * 8]     = acc[nt][2] * f1;
                stage[r8 + nt * 8 + 1] = acc[nt][3] * f1;
            }
        }
        __syncthreads();
        int tn = tid & 7, tc = tid >> 3;
#pragma unroll
        for (int i = 0; i < 4; i++) {
            int row = tn + 8 * i;
            int pa = pas[pass * 32 + row];
#pragma unroll
            for (int j = 0; j < 8; j++) {
                int c = tc * 8 + j;
                out[pa + c * HW] += stage[row * 264 + c];
            }
        }
    }
}

// ---------------------------------------------------------------- launcher
extern "C" void kernel_launch(void* const* d_in, const int* in_sizes, int n_in,
                              void* d_out, int out_size) {
    const float* x   = (const float*)d_in[0];
    const float* Wq  = (const float*)d_in[1];
    const float* bq  = (const float*)d_in[2];
    const float* q_s = (const float*)d_in[3];
    const float* q_o = (const float*)d_in[4];
    const float* q_m = (const float*)d_in[5];
    const float* q_v = (const float*)d_in[6];
    const float* Wk  = (const float*)d_in[7];
    const float* bk  = (const float*)d_in[8];
    const float* k_s = (const float*)d_in[9];
    const float* k_o = (const float*)d_in[10];
    const float* k_m = (const float*)d_in[11];
    const float* k_v = (const float*)d_in[12];
    const float* Wv  = (const float*)d_in[13];
    const float* bv  = (const float*)d_in[14];
    const float* gam = (const float*)d_in[15];
    float* out = (float*)d_out;

    cudaFuncSetAttribute(attn, cudaFuncAttributeMaxDynamicSharedMemorySize, ASMEM);

    prep_wall<<<224, 256>>>(Wq, Wk, Wv);
    prep_bn<<<1, 32>>>(bq, q_s, q_o, q_m, q_v, bk, k_s, k_o, k_m, k_v);
    prep_pix<<<dim3(6, 232), 256>>>();
    copy_x<<<4096, 256>>>((const float4*)x, (float4*)out);
    qkv_gemm<<<dim3(7, 24, 232), 256>>>(x, bv);
    v_pack<<<TOTPIX / 32, 256>>>();
    combine_qk<<<dim3(96, 232), 256>>>();
    // win regions (0..11): disjoint pixels within launch -> plain RMW
    attn<<<dim3(16, 96), 256, ASMEM>>>(gam, out, 0);
    // shift regions (12..28): partition of image -> plain RMW
    attn<<<dim3(24, 136), 256, ASMEM>>>(gam, out, 96);
}